// round 14
// baseline (speedup 1.0000x reference)
#include <cuda_runtime.h>
#include <cuda_fp16.h>
#include <cuda_bf16.h>
#include <cstdint>

#define B_  4
#define S_  2048
#define HID_ 2048
#define NH_ 16
#define NKV_ 4
#define D_  128
#define EPS_ 1e-6f
#define SCALE_ 0.08838834764831845f   // 128^-0.5
#define MAXB_ 11.5f                   // score bound: sqrt(128)*sqrt(128)*SCALE=11.314

#define MT_  8192     // B*S rows
#define KK_  2048     // GEMM K (always HID_)
#define NQKV_ 5120    // fused projection width: 4096 (q,gate) + 512 (k) + 512 (v)

// ---------------- scratch (static __device__, allocation-free) ----------------
__device__ float g_qkv [(size_t)MT_*NQKV_];
__device__ float g_octx[(size_t)MT_*2048];
__device__ float g_rowsum[(size_t)B_*NH_*S_];
__device__ __half g_ahi[(size_t)MT_*KK_],  g_alo[(size_t)MT_*KK_];
__device__ __half g_wqkvh[(size_t)NQKV_*KK_];
__device__ __half g_woh[(size_t)2048*KK_];
__device__ __half g_ohi[(size_t)MT_*2048], g_olo[(size_t)MT_*2048];
__device__ __half g_qh[(size_t)B_*NH_*S_*D_], g_ql[(size_t)B_*NH_*S_*D_];
__device__ __half g_kh[(size_t)B_*NKV_*S_*D_];
__device__ __nv_bfloat16 g_vth[(size_t)B_*NKV_*D_*S_], g_vtl[(size_t)B_*NKV_*D_*S_];

// ================= PTX helpers (family-target-safe: sm_80+ features only) =====
__device__ __forceinline__ uint32_t smem_u32(const void* p) {
    uint32_t a;
    asm("{ .reg .u64 t; cvta.to.shared.u64 t, %1; cvt.u32.u64 %0, t; }" : "=r"(a) : "l"(p));
    return a;
}
__device__ __forceinline__ void cp16(uint32_t s, const void* g) {
    asm volatile("cp.async.cg.shared.global [%0], [%1], 16;" :: "r"(s), "l"(g));
}
__device__ __forceinline__ void ldm4(uint32_t* r, uint32_t addr) {
    asm volatile("ldmatrix.sync.aligned.m8n8.x4.shared.b16 {%0,%1,%2,%3}, [%4];"
                 : "=r"(r[0]), "=r"(r[1]), "=r"(r[2]), "=r"(r[3]) : "r"(addr));
}
__device__ __forceinline__ void mma_f16(float* c, const uint32_t* a, const uint32_t* b) {
    asm volatile("mma.sync.aligned.m16n8k16.row.col.f32.f16.f16.f32 "
                 "{%0,%1,%2,%3}, {%4,%5,%6,%7}, {%8,%9}, {%0,%1,%2,%3};"
                 : "+f"(c[0]), "+f"(c[1]), "+f"(c[2]), "+f"(c[3])
                 : "r"(a[0]), "r"(a[1]), "r"(a[2]), "r"(a[3]), "r"(b[0]), "r"(b[1]));
}
__device__ __forceinline__ void mma_bf16(float* c, const uint32_t* a, const uint32_t* b) {
    asm volatile("mma.sync.aligned.m16n8k16.row.col.f32.bf16.bf16.f32 "
                 "{%0,%1,%2,%3}, {%4,%5,%6,%7}, {%8,%9}, {%0,%1,%2,%3};"
                 : "+f"(c[0]), "+f"(c[1]), "+f"(c[2]), "+f"(c[3])
                 : "r"(a[0]), "r"(a[1]), "r"(a[2]), "r"(a[3]), "r"(b[0]), "r"(b[1]));
}
__device__ __forceinline__ uint32_t phys(int r, int c) {
    return (uint32_t)(r * 128 + ((c ^ (r & 7)) << 4));
}
__device__ __forceinline__ uint32_t phys256(int r, int c) {
    return (uint32_t)(r * 256 + (((c & 7) ^ (r & 7)) << 4) + ((c & 8) << 4));
}
__device__ __forceinline__ void split_pack_h(float a, float b, uint32_t& hi, uint32_t& lo) {
    __half ha = __float2half(a), hb = __float2half(b);
    __half la = __float2half(a - __half2float(ha));
    __half lb = __float2half(b - __half2float(hb));
    __half2 H(ha, hb), L(la, lb);
    hi = *(uint32_t*)&H;
    lo = *(uint32_t*)&L;
}
__device__ __forceinline__ void split_pack_b(float a, float b, uint32_t& hi, uint32_t& lo) {
    __nv_bfloat16 ha = __float2bfloat16(a), hb = __float2bfloat16(b);
    __nv_bfloat16 la = __float2bfloat16(a - __bfloat162float(ha));
    __nv_bfloat16 lb = __float2bfloat16(b - __bfloat162float(hb));
    __nv_bfloat162 H(ha, hb), L(la, lb);
    hi = *(uint32_t*)&H;
    lo = *(uint32_t*)&L;
}

#define ASTG_BYTES 49152         // attention stage: Kh|Vh|Vl, 16KB each
#define GSTG_BYTES 65536         // gemm stage: Ah 16KB | Al 16KB | B 32KB
#define GEMM_SMEM (3 * GSTG_BYTES)

// ==== fp16 2-term GEMM, 128x256 tile: C = (Ah+Al)*Bh^T, 3-stage pipe ====
__global__ __launch_bounds__(256, 1) void gemm_f16x2(
    const __half* __restrict__ Ahi, const __half* __restrict__ Alo,
    const __half* __restrict__ Bhi, float* __restrict__ C, int N) {
    extern __shared__ char smem[];
    const uint32_t sb = smem_u32(smem);
    const int tid = threadIdx.x, wid = tid >> 5, lane = tid & 31;
    const int m0 = blockIdx.y * 128, n0 = blockIdx.x * 256;
    const int NKI = KK_ / 64;    // 32 iters

    const __half* ah = Ahi + (size_t)m0 * KK_;
    const __half* al = Alo + (size_t)m0 * KK_;
    const __half* bh = Bhi + (size_t)n0 * KK_;

    auto load_stage = [&](int st, int it) {
        const uint32_t base = sb + st * GSTG_BYTES;
        const int k0 = it * 64;
        for (int q = tid; q < 4096; q += 256) {
            int reg = q >> 10;
            if (reg == 0) {
                int r = (q & 1023) >> 3, c = q & 7;
                cp16(base + phys(r, c), ah + (size_t)r * KK_ + k0 + c * 8);
            } else if (reg == 1) {
                int r = (q & 1023) >> 3, c = q & 7;
                cp16(base + 16384 + phys(r, c), al + (size_t)r * KK_ + k0 + c * 8);
            } else {
                int r = (q - 2048) >> 3, c = q & 7;
                cp16(base + 32768 + phys(r, c), bh + (size_t)r * KK_ + k0 + c * 8);
            }
        }
        asm volatile("cp.async.commit_group;" ::: "memory");
    };

    load_stage(0, 0);
    load_stage(1, 1);
    load_stage(2, 2);

    const int wm = (wid & 3) * 32;
    const int wn = (wid >> 2) * 128;
    float acc[2][16][4];
#pragma unroll
    for (int i = 0; i < 2; i++)
#pragma unroll
        for (int j = 0; j < 16; j++)
#pragma unroll
            for (int q = 0; q < 4; q++) acc[i][j][q] = 0.0f;

    const int fr = (lane & 7) + ((lane >> 3) & 1) * 8;
    const int fc = lane >> 4;

    for (int i = 0; i < NKI; i++) {
        if (i < NKI - 2)       asm volatile("cp.async.wait_group 2;" ::: "memory");
        else if (i == NKI - 2) asm volatile("cp.async.wait_group 1;" ::: "memory");
        else                   asm volatile("cp.async.wait_group 0;" ::: "memory");
        __syncthreads();

        const int st = i % 3;
        const uint32_t bA = sb + st * GSTG_BYTES;
        const uint32_t bAl = bA + 16384, bB = bA + 32768;
#pragma unroll
        for (int s = 0; s < 4; s++) {
            uint32_t ahf[2][4], alf[2][4];
#pragma unroll
            for (int mi = 0; mi < 2; mi++) {
                int r = wm + mi * 16 + fr;
                uint32_t off = phys(r, s * 2 + fc);
                ldm4(ahf[mi], bA + off);
                ldm4(alf[mi], bAl + off);
            }
#pragma unroll
            for (int ng = 0; ng < 8; ng++) {
                int r = wn + ng * 16 + fr;
                uint32_t t[4];
                ldm4(t, bB + phys(r, s * 2 + fc));
                uint32_t b0[2] = {t[0], t[2]};
                uint32_t b1[2] = {t[1], t[3]};
#pragma unroll
                for (int mi = 0; mi < 2; mi++) {
                    mma_f16(acc[mi][ng * 2],     ahf[mi], b0);
                    mma_f16(acc[mi][ng * 2],     alf[mi], b0);
                    mma_f16(acc[mi][ng * 2 + 1], ahf[mi], b1);
                    mma_f16(acc[mi][ng * 2 + 1], alf[mi], b1);
                }
            }
        }
        __syncthreads();
        if (i + 3 < NKI) load_stage(st, i + 3);
    }

#pragma unroll
    for (int mi = 0; mi < 2; mi++) {
        int r0 = m0 + wm + mi * 16 + (lane >> 2);
#pragma unroll
        for (int nf = 0; nf < 16; nf++) {
            int col = n0 + wn + nf * 8 + (lane & 3) * 2;
            *(float2*)(C + (size_t)r0 * N + col)       = make_float2(acc[mi][nf][0], acc[mi][nf][1]);
            *(float2*)(C + (size_t)(r0 + 8) * N + col) = make_float2(acc[mi][nf][2], acc[mi][nf][3]);
        }
    }
}

// ============ fp32 -> fp16 hi/lo split ============
__global__ __launch_bounds__(256) void split_fp16(const float* __restrict__ x,
                                                  __half* __restrict__ hi,
                                                  __half* __restrict__ lo,
                                                  int n4) {
    int i = blockIdx.x * 256 + threadIdx.x;
    if (i >= n4) return;
    float4 v = ((const float4*)x)[i];
    uint32_t h01, l01, h23, l23;
    split_pack_h(v.x, v.y, h01, l01);
    split_pack_h(v.z, v.w, h23, l23);
    ((uint32_t*)hi)[2 * i]     = h01;
    ((uint32_t*)hi)[2 * i + 1] = h23;
    ((uint32_t*)lo)[2 * i]     = l01;
    ((uint32_t*)lo)[2 * i + 1] = l23;
}

// ============ gate: (octx * sigmoid(gate)) -> fp16 hi/lo ============
__global__ __launch_bounds__(256) void gate_split(const float* __restrict__ qkv,
                                                  const float* __restrict__ octx,
                                                  __half* __restrict__ hi,
                                                  __half* __restrict__ lo) {
    size_t i4 = (size_t)blockIdx.x * blockDim.x + threadIdx.x;
    size_t e = i4 * 4;
    int d = (int)(e % D_);
    int h = (int)((e / D_) % NH_);
    size_t bs = e / (D_ * NH_);
    const float4 gv = *(const float4*)(qkv + bs * NQKV_ + h * (2 * D_) + D_ + d);
    float4 ov = *(const float4*)(octx + e);
    ov.x *= 1.0f / (1.0f + __expf(-gv.x));
    ov.y *= 1.0f / (1.0f + __expf(-gv.y));
    ov.z *= 1.0f / (1.0f + __expf(-gv.z));
    ov.w *= 1.0f / (1.0f + __expf(-gv.w));
    uint32_t h01, l01, h23, l23;
    split_pack_h(ov.x, ov.y, h01, l01);
    split_pack_h(ov.z, ov.w, h23, l23);
    ((uint32_t*)hi)[2 * i4]     = h01;
    ((uint32_t*)hi)[2 * i4 + 1] = h23;
    ((uint32_t*)lo)[2 * i4]     = l01;
    ((uint32_t*)lo)[2 * i4 + 1] = l23;
}

// ============ W[K,N] fp32 -> Wt fp16 [N,K] (round only) ============
__global__ __launch_bounds__(256) void transpose_half(const float* __restrict__ W,
                                                      __half* __restrict__ thi,
                                                      int N) {
    __shared__ float t[32][33];
    const int n0 = blockIdx.x * 32, k0 = blockIdx.y * 32;
    const int tx = threadIdx.x, ty = threadIdx.y;
    for (int i = ty; i < 32; i += 8)
        t[i][tx] = W[(size_t)(k0 + i) * N + n0 + tx];
    __syncthreads();
    for (int i = ty; i < 32; i += 8)
        thi[(size_t)(n0 + i) * KK_ + k0 + tx] = __float2half(t[tx][i]);
}

// ============ V (cols [4608,5120) of qkv) -> V^T bf16 hi/lo (b,kh,d,s) ========
__global__ __launch_bounds__(256) void v_trans_split(const float* __restrict__ qkv,
                                                     __nv_bfloat16* __restrict__ vth,
                                                     __nv_bfloat16* __restrict__ vtl) {
    __shared__ float t[32][33];
    const int bk = blockIdx.z;
    const int b = bk >> 2, kv = bk & 3;
    const int s0 = blockIdx.x * 32, d0 = blockIdx.y * 32;
    const int tx = threadIdx.x, ty = threadIdx.y;
    for (int i = ty; i < 32; i += 8)
        t[i][tx] = qkv[(size_t)(b * S_ + s0 + i) * NQKV_ + 4608 + kv * D_ + d0 + tx];
    __syncthreads();
    for (int i = ty; i < 32; i += 8) {
        float val = t[tx][i];
        __nv_bfloat16 h = __float2bfloat16(val);
        __nv_bfloat16 l = __float2bfloat16(val - __bfloat162float(h));
        size_t o = ((size_t)(b * NKV_ + kv) * D_ + d0 + i) * S_ + s0 + tx;
        vth[o] = h;
        vtl[o] = l;
    }
}

// ---------------- RMSNorm + RoPE ----------------
__global__ __launch_bounds__(128) void norm_rope_q_h(const float* __restrict__ qkv,
                                                     const float* __restrict__ cosb,
                                                     const float* __restrict__ sinb,
                                                     const float* __restrict__ w,
                                                     __half* __restrict__ qh,
                                                     __half* __restrict__ ql) {
    const int idx = blockIdx.x;
    const int h = idx % NH_;
    const int bs = idx / NH_;
    const int d = threadIdx.x;
    const float* x = qkv + (size_t)bs * NQKV_ + h * (2 * D_);
    float xv = x[d];
    float sq = xv * xv;
#pragma unroll
    for (int o = 16; o > 0; o >>= 1) sq += __shfl_xor_sync(0xffffffffu, sq, o);
    __shared__ float wsum[4];
    __shared__ float xs[D_];
    if ((d & 31) == 0) wsum[d >> 5] = sq;
    __syncthreads();
    float total = wsum[0] + wsum[1] + wsum[2] + wsum[3];
    float xn = xv * rsqrtf(total * (1.0f / D_) + EPS_) * (1.0f + w[d]);
    xs[d] = xn;
    __syncthreads();
    float c = cosb[(size_t)bs * D_ + d];
    float sn = sinb[(size_t)bs * D_ + d];
    float rot = (d < D_ / 2) ? -xs[d + D_ / 2] : xs[d - D_ / 2];
    float val = xn * c + rot * sn;
    const int b = bs / S_, s = bs % S_;
    size_t o = (((size_t)b * NH_ + h) * S_ + s) * D_ + d;
    __half hi = __float2half(val);
    qh[o] = hi;
    ql[o] = __float2half(val - __half2float(hi));
}

__global__ __launch_bounds__(128) void norm_rope_k_h(const float* __restrict__ qkv,
                                                     const float* __restrict__ cosb,
                                                     const float* __restrict__ sinb,
                                                     const float* __restrict__ w,
                                                     __half* __restrict__ kh) {
    const int idx = blockIdx.x;
    const int kv = idx % NKV_;
    const int bs = idx / NKV_;
    const int d = threadIdx.x;
    const float* x = qkv + (size_t)bs * NQKV_ + 4096 + kv * D_;
    float xv = x[d];
    float sq = xv * xv;
#pragma unroll
    for (int o = 16; o > 0; o >>= 1) sq += __shfl_xor_sync(0xffffffffu, sq, o);
    __shared__ float wsum[4];
    __shared__ float xs[D_];
    if ((d & 31) == 0) wsum[d >> 5] = sq;
    __syncthreads();
    float total = wsum[0] + wsum[1] + wsum[2] + wsum[3];
    float xn = xv * rsqrtf(total * (1.0f / D_) + EPS_) * (1.0f + w[d]);
    xs[d] = xn;
    __syncthreads();
    float c = cosb[(size_t)bs * D_ + d];
    float sn = sinb[(size_t)bs * D_ + d];
    float rot = (d < D_ / 2) ? -xs[d + D_ / 2] : xs[d - D_ / 2];
    float val = xn * c + rot * sn;
    const int b = bs / S_, s = bs % S_;
    kh[(((size_t)b * NKV_ + kv) * S_ + s) * D_ + d] = __float2half(val);
}

// ===== single-pass fused attention: QK fp16x2 (Q hi/lo, K hi), PV bf16x3 =====
// smem: Q hi/lo 64KB + 2 stages of (Kh fp16 16KB; Vh,Vl bf16 32KB) = 160KB
#define P2_SMEM (65536 + 2 * ASTG_BYTES)
__global__ __launch_bounds__(256, 1) void attn_fused(
    const __half* __restrict__ qh, const __half* __restrict__ ql,
    const __half* __restrict__ khb,
    const __nv_bfloat16* __restrict__ vth, const __nv_bfloat16* __restrict__ vtl,
    float* __restrict__ rowsum,
    float* __restrict__ P, float* __restrict__ octx) {
    extern __shared__ char smem[];
    const uint32_t sb = smem_u32(smem);
    const int tid = threadIdx.x, wid = tid >> 5, lane = tid & 31;
    const int qt = blockIdx.x, bh = blockIdx.y;
    const int b = bh >> 4, h = bh & 15, kv = h >> 2;
    const int q0 = qt * 128;
    const int nk = 2 * qt + 2;
    const __half* qhp = qh + ((size_t)(b * NH_ + h) * S_ + q0) * D_;
    const __half* qlp = ql + ((size_t)(b * NH_ + h) * S_ + q0) * D_;
    const __half* khp = khb + (size_t)(b * NKV_ + kv) * S_ * D_;
    const __nv_bfloat16* vhp = vth + (size_t)(b * NKV_ + kv) * D_ * S_;
    const __nv_bfloat16* vlp = vtl + (size_t)(b * NKV_ + kv) * D_ * S_;

    for (int q = tid; q < 2048; q += 256) {
        int r = q >> 4, c = q & 15;
        uint32_t off = phys256(r, c);
        cp16(sb + off, qhp + (size_t)r * D_ + c * 8);
        cp16(sb + 32768 + off, qlp + (size_t)r * D_ + c * 8);
    }
    auto load_stage = [&](int st, int kt) {
        uint32_t base = sb + 65536 + st * ASTG_BYTES;
        const __half* sh = khp + (size_t)kt * 64 * D_;
        for (int q = tid; q < 1024; q += 256) {
            int r = q >> 4, c = q & 15;
            cp16(base + phys256(r, c), sh + (size_t)r * D_ + c * 8);
        }
        for (int q = tid; q < 1024; q += 256) {
            int r = q >> 3, c = q & 7;
            uint32_t off = phys(r, c);
            cp16(base + 16384 + off, vhp + (size_t)r * S_ + kt * 64 + c * 8);
            cp16(base + 32768 + off, vlp + (size_t)r * S_ + kt * 64 + c * 8);
        }
    };
    load_stage(0, 0);
    asm volatile("cp.async.commit_group;" ::: "memory");
    load_stage(1, 1);
    asm volatile("cp.async.commit_group;" ::: "memory");

    const int wm = (wid & 3) * 32, wn = (wid >> 2) * 32;
    const int fr = (lane & 7) + ((lane >> 3) & 1) * 8;
    const int fc = lane >> 4;

    float lsum[4] = {0.0f, 0.0f, 0.0f, 0.0f};
    float pv[2][16][4];
#pragma unroll
    for (int mi = 0; mi < 2; mi++)
#pragma unroll
        for (int n = 0; n < 16; n++)
#pragma unroll
            for (int q = 0; q < 4; q++) pv[mi][n][q] = 0.0f;

    for (int kt = 0; kt < nk; kt++) {
        if (kt == nk - 1) asm volatile("cp.async.wait_group 0;" ::: "memory");
        else              asm volatile("cp.async.wait_group 1;" ::: "memory");
        __syncthreads();
        const uint32_t stg = sb + 65536 + (kt & 1) * ASTG_BYTES;
        const uint32_t bK = stg, bV = stg + 16384, bVl = stg + 32768;

        float acc[2][4][4];
#pragma unroll
        for (int i = 0; i < 2; i++)
#pragma unroll
            for (int j = 0; j < 4; j++)
#pragma unroll
                for (int q = 0; q < 4; q++) acc[i][j][q] = 0.0f;

#pragma unroll
        for (int ks = 0; ks < 8; ks++) {
            uint32_t ahf[2][4], alf[2][4], bhf[4][2];
#pragma unroll
            for (int mi = 0; mi < 2; mi++) {
                uint32_t off = phys256(wm + mi * 16 + fr, ks * 2 + fc);
                ldm4(ahf[mi], sb + off);
                ldm4(alf[mi], sb + 32768 + off);
            }
#pragma unroll
            for (int ng = 0; ng < 2; ng++) {
                uint32_t off = phys256(wn + ng * 16 + fr, ks * 2 + fc);
                uint32_t t[4];
                ldm4(t, bK + off);
                bhf[ng * 2][0] = t[0]; bhf[ng * 2][1] = t[2];
                bhf[ng * 2 + 1][0] = t[1]; bhf[ng * 2 + 1][1] = t[3];
            }
#pragma unroll
            for (int mi = 0; mi < 2; mi++)
#pragma unroll
                for (int n = 0; n < 4; n++) {
                    mma_f16(acc[mi][n], ahf[mi], bhf[n]);
                    mma_f16(acc[mi][n], alf[mi], bhf[n]);
                }
        }

        // e = exp(s*SCALE - MAXB)  (masked -> 0); accumulate rowsum; write P
        const bool full = (kt * 64 + 63 <= q0);
#pragma unroll
        for (int mi = 0; mi < 2; mi++)
#pragma unroll
            for (int n = 0; n < 4; n++)
#pragma unroll
                for (int e = 0; e < 4; e++) {
                    const int slot = mi * 2 + (e >> 1);
                    float p = __expf(acc[mi][n][e] * SCALE_ - MAXB_);
                    if (!full) {
                        int gi = q0 + wm + mi * 16 + (lane >> 2) + (e >> 1) * 8;
                        int gj = kt * 64 + wn + n * 8 + (lane & 3) * 2 + (e & 1);
                        if (gj > gi) p = 0.0f;
                    }
                    acc[mi][n][e] = p;
                    lsum[slot] += p;
                }
#pragma unroll
        for (int mi = 0; mi < 2; mi++) {
            int r0 = q0 + wm + mi * 16 + (lane >> 2);
#pragma unroll
            for (int n = 0; n < 4; n++) {
                int col = kt * 64 + wn + n * 8 + (lane & 3) * 2;
                *(float2*)(P + ((size_t)bh * S_ + r0) * S_ + col) =
                    make_float2(acc[mi][n][0], acc[mi][n][1]);
                *(float2*)(P + ((size_t)bh * S_ + r0 + 8) * S_ + col) =
                    make_float2(acc[mi][n][2], acc[mi][n][3]);
            }
        }

        // PV: e (A frags, bf16 hi/lo) x V^T (B frags, bf16 hi/lo), 3-term
#pragma unroll
        for (int ksl = 0; ksl < 2; ksl++) {
            uint32_t pah[2][4], pal[2][4];
#pragma unroll
            for (int mi = 0; mi < 2; mi++) {
                const int n0 = ksl * 2, n1 = ksl * 2 + 1;
                split_pack_b(acc[mi][n0][0], acc[mi][n0][1], pah[mi][0], pal[mi][0]);
                split_pack_b(acc[mi][n0][2], acc[mi][n0][3], pah[mi][1], pal[mi][1]);
                split_pack_b(acc[mi][n1][0], acc[mi][n1][1], pah[mi][2], pal[mi][2]);
                split_pack_b(acc[mi][n1][2], acc[mi][n1][3], pah[mi][3], pal[mi][3]);
            }
            const int cc = (wn >> 3) + ksl * 2;
#pragma unroll
            for (int dg = 0; dg < 8; dg++) {
                uint32_t t[4], bh2[2][2], bl2[2][2];
                ldm4(t, bV + phys(dg * 16 + fr, cc + fc));
                bh2[0][0] = t[0]; bh2[0][1] = t[2];
                bh2[1][0] = t[1]; bh2[1][1] = t[3];
                ldm4(t, bVl + phys(dg * 16 + fr, cc + fc));
                bl2[0][0] = t[0]; bl2[0][1] = t[2];
                bl2[1][0] = t[1]; bl2[1][1] = t[3];
#pragma unroll
                for (int mi = 0; mi < 2; mi++)
#pragma unroll
                    for (int sub = 0; sub < 2; sub++) {
                        const int nf = dg * 2 + sub;
                        mma_bf16(pv[mi][nf], pah[mi], bh2[sub]);
                        mma_bf16(pv[mi][nf], pah[mi], bl2[sub]);
                        mma_bf16(pv[mi][nf], pal[mi], bh2[sub]);
                    }
            }
        }
        __syncthreads();
        if (kt + 2 < nk) {
            load_stage(kt & 1, kt + 2);
            asm volatile("cp.async.commit_group;" ::: "memory");
        }
    }

    // reduce lsum across the 4 lanes of each quad
#pragma unroll
    for (int o = 1; o < 4; o <<= 1)
#pragma unroll
        for (int slot = 0; slot < 4; slot++)
            lsum[slot] += __shfl_xor_sync(0xffffffffu, lsum[slot], o);

    // combine the two col-warp groups; normalize; store octx + rowsum
    __syncthreads();
    float* ob = (float*)smem;          // 128 rows x pitch 136 floats
    float* lrow = ob + 128 * 136;
    if (wn == 32) {
#pragma unroll
        for (int mi = 0; mi < 2; mi++) {
            int r0 = wm + mi * 16 + (lane >> 2);
#pragma unroll
            for (int nf = 0; nf < 16; nf++) {
                int d = nf * 8 + (lane & 3) * 2;
                *(float2*)&ob[(size_t)r0 * 136 + d]       = make_float2(pv[mi][nf][0], pv[mi][nf][1]);
                *(float2*)&ob[(size_t)(r0 + 8) * 136 + d] = make_float2(pv[mi][nf][2], pv[mi][nf][3]);
            }
            if ((lane & 3) == 0) {
                lrow[r0]     = lsum[mi * 2];
                lrow[r0 + 8] = lsum[mi * 2 + 1];
            }
        }
    }
    __syncthreads();
    if (wn == 0) {
#pragma unroll
        for (int mi = 0; mi < 2; mi++) {
            int r0 = wm + mi * 16 + (lane >> 2);
            float lt0 = lsum[mi * 2] + lrow[r0];
            float lt1 = lsum[mi * 2 + 1] + lrow[r0 + 8];
            float inv0 = 1.0f / lt0;
            float inv1 = 1.0f / lt1;
            if ((lane & 3) == 0) {
                rowsum[(size_t)bh * S_ + q0 + r0]     = lt0;
                rowsum[(size_t)bh * S_ + q0 + r0 + 8] = lt1;
            }
#pragma unroll
            for (int nf = 0; nf < 16; nf++) {
                int d = nf * 8 + (lane & 3) * 2;
                float2 a0 = *(float2*)&ob[(size_t)r0 * 136 + d];
                float2 a1 = *(float2*)&ob[(size_t)(r0 + 8) * 136 + d];
                float* o0 = octx + ((size_t)(b * S_ + q0 + r0) * NH_ + h) * D_ + d;
                float* o1 = octx + ((size_t)(b * S_ + q0 + r0 + 8) * NH_ + h) * D_ + d;
                *(float2*)o0 = make_float2((pv[mi][nf][0] + a0.x) * inv0, (pv[mi][nf][1] + a0.y) * inv0);
                *(float2*)o1 = make_float2((pv[mi][nf][2] + a1.x) * inv1, (pv[mi][nf][3] + a1.y) * inv1);
            }
        }
    }
}

// -------- fixup: normalize written P region by 1/rowsum, zero the rest --------
__global__ __launch_bounds__(128) void normalize_zero(float* __restrict__ P,
                                                      const float* __restrict__ rowsum) {
    const int row = blockIdx.x;          // bh*S + i
    const int i = row & (S_ - 1);
    const int jend = ((i >> 7) + 1) << 7;
    const float inv = 1.0f / rowsum[row];
    float* p = P + (size_t)row * S_;
    const int t4 = threadIdx.x * 4;
    for (int j = t4; j < jend; j += 512) {
        float4 v = *(float4*)(p + j);
        v.x *= inv; v.y *= inv; v.z *= inv; v.w *= inv;
        *(float4*)(p + j) = v;
    }
    const float4 z = {0, 0, 0, 0};
    for (int j = jend + t4; j < S_; j += 512)
        *(float4*)(p + j) = z;
}

// ---------------- launch ----------------
extern "C" void kernel_launch(void* const* d_in, const int* in_sizes, int n_in,
                              void* d_out, int out_size) {
    const float* hidden = (const float*)d_in[0];
    const float* cosb   = (const float*)d_in[1];
    const float* sinb   = (const float*)d_in[2];
    const float* Wq     = (const float*)d_in[4];
    const float* Wk     = (const float*)d_in[5];
    const float* Wv     = (const float*)d_in[6];
    const float* Wo     = (const float*)d_in[7];
    const float* qnw    = (const float*)d_in[8];
    const float* knw    = (const float*)d_in[9];

    float* out = (float*)d_out;
    const size_t ao_elems = (size_t)MT_ * HID_;
    float* P = out + ao_elems;

    float *qkv, *octx, *rsum;
    __half *ahi, *alo, *wqh, *woh, *ohi, *olo, *qhv, *qlv, *khv;
    __nv_bfloat16 *vth, *vtl;
    cudaGetSymbolAddress((void**)&qkv,  g_qkv);
    cudaGetSymbolAddress((void**)&octx, g_octx);
    cudaGetSymbolAddress((void**)&rsum, g_rowsum);
    cudaGetSymbolAddress((void**)&ahi,  g_ahi);
    cudaGetSymbolAddress((void**)&alo,  g_alo);
    cudaGetSymbolAddress((void**)&wqh,  g_wqkvh);
    cudaGetSymbolAddress((void**)&woh,  g_woh);
    cudaGetSymbolAddress((void**)&ohi,  g_ohi);
    cudaGetSymbolAddress((void**)&olo,  g_olo);
    cudaGetSymbolAddress((void**)&qhv,  g_qh);
    cudaGetSymbolAddress((void**)&qlv,  g_ql);
    cudaGetSymbolAddress((void**)&khv,  g_kh);
    cudaGetSymbolAddress((void**)&vth,  g_vth);
    cudaGetSymbolAddress((void**)&vtl,  g_vtl);

    cudaFuncSetAttribute(gemm_f16x2, cudaFuncAttributeMaxDynamicSharedMemorySize, GEMM_SMEM);
    cudaFuncSetAttribute(attn_fused, cudaFuncAttributeMaxDynamicSharedMemorySize, P2_SMEM);

    // weight transpose (hi only, fused QKV layout), hidden split (hi/lo)
    transpose_half<<<dim3(4096 / 32, KK_ / 32), dim3(32, 8)>>>(Wq, wqh, 4096);
    transpose_half<<<dim3(512 / 32,  KK_ / 32), dim3(32, 8)>>>(Wk, wqh + (size_t)4096 * KK_, 512);
    transpose_half<<<dim3(512 / 32,  KK_ / 32), dim3(32, 8)>>>(Wv, wqh + (size_t)4608 * KK_, 512);
    transpose_half<<<dim3(2048 / 32, KK_ / 32), dim3(32, 8)>>>(Wo, woh, 2048);
    {
        int n4 = (int)((size_t)MT_ * KK_ / 4);
        split_fp16<<<(n4 + 255) / 256, 256>>>(hidden, ahi, alo, n4);
    }

    // fused QKV projection (fp16 2-term, 128x256 tiles)
    gemm_f16x2<<<dim3(NQKV_ / 256, MT_ / 128), 256, GEMM_SMEM>>>(ahi, alo, wqh, qkv, NQKV_);

    // norm + rope; V transpose (bf16 hi/lo)
    norm_rope_q_h<<<B_ * S_ * NH_, 128>>>(qkv, cosb, sinb, qnw, qhv, qlv);
    norm_rope_k_h<<<B_ * S_ * NKV_, 128>>>(qkv, cosb, sinb, knw, khv);
    v_trans_split<<<dim3(S_ / 32, D_ / 32, B_ * NKV_), dim3(32, 8)>>>(qkv, vth, vtl);

    // fused single-pass attention + P normalize/zero fixup
    attn_fused<<<dim3(S_ / 128, B_ * NH_), 256, P2_SMEM>>>(qhv, qlv, khv, vth, vtl,
                                                           rsum, P, octx);
    normalize_zero<<<B_ * NH_ * S_, 128>>>(P, rsum);

    // gate + split + output projection (fp16 2-term, 128x256 tiles)
    gate_split<<<(int)(((size_t)MT_ * 2048 / 4) / 256), 256>>>(qkv, octx, ohi, olo);
    gemm_f16x2<<<dim3(2048 / 256, MT_ / 128), 256, GEMM_SMEM>>>(ohi, olo, woh, out, 2048);
}

// round 15
// speedup vs baseline: 1.0259x; 1.0259x over previous
#include <cuda_runtime.h>
#include <cuda_fp16.h>
#include <cuda_bf16.h>
#include <cstdint>

#define B_  4
#define S_  2048
#define HID_ 2048
#define NH_ 16
#define NKV_ 4
#define D_  128
#define EPS_ 1e-6f
#define SCALE_ 0.08838834764831845f   // 128^-0.5
#define MAXB_ 11.5f                   // score bound: sqrt(128)*sqrt(128)*SCALE=11.314

#define MT_  8192     // B*S rows
#define KK_  2048     // GEMM K (always HID_)
#define NQKV_ 5120    // fused projection width: 4096 (q,gate) + 512 (k) + 512 (v)

// ---------------- scratch (static __device__, allocation-free) ----------------
__device__ float g_qkv [(size_t)MT_*NQKV_];
__device__ float g_octx[(size_t)MT_*2048];
__device__ float g_rowsum[(size_t)B_*NH_*S_];
__device__ __half g_ahi[(size_t)MT_*KK_],  g_alo[(size_t)MT_*KK_];
__device__ __half g_wqkvh[(size_t)NQKV_*KK_];
__device__ __half g_woh[(size_t)2048*KK_];
__device__ __half g_ohi[(size_t)MT_*2048], g_olo[(size_t)MT_*2048];
__device__ __half g_qh[(size_t)B_*NH_*S_*D_], g_ql[(size_t)B_*NH_*S_*D_];
__device__ __half g_kh[(size_t)B_*NKV_*S_*D_];
__device__ __nv_bfloat16 g_vth[(size_t)B_*NKV_*D_*S_], g_vtl[(size_t)B_*NKV_*D_*S_];

// ================= PTX helpers (family-target-safe: sm_80+ features only) =====
__device__ __forceinline__ uint32_t smem_u32(const void* p) {
    uint32_t a;
    asm("{ .reg .u64 t; cvta.to.shared.u64 t, %1; cvt.u32.u64 %0, t; }" : "=r"(a) : "l"(p));
    return a;
}
__device__ __forceinline__ void cp16(uint32_t s, const void* g) {
    asm volatile("cp.async.cg.shared.global [%0], [%1], 16;" :: "r"(s), "l"(g));
}
__device__ __forceinline__ void ldm4(uint32_t* r, uint32_t addr) {
    asm volatile("ldmatrix.sync.aligned.m8n8.x4.shared.b16 {%0,%1,%2,%3}, [%4];"
                 : "=r"(r[0]), "=r"(r[1]), "=r"(r[2]), "=r"(r[3]) : "r"(addr));
}
__device__ __forceinline__ void mma_f16(float* c, const uint32_t* a, const uint32_t* b) {
    asm volatile("mma.sync.aligned.m16n8k16.row.col.f32.f16.f16.f32 "
                 "{%0,%1,%2,%3}, {%4,%5,%6,%7}, {%8,%9}, {%0,%1,%2,%3};"
                 : "+f"(c[0]), "+f"(c[1]), "+f"(c[2]), "+f"(c[3])
                 : "r"(a[0]), "r"(a[1]), "r"(a[2]), "r"(a[3]), "r"(b[0]), "r"(b[1]));
}
__device__ __forceinline__ void mma_bf16(float* c, const uint32_t* a, const uint32_t* b) {
    asm volatile("mma.sync.aligned.m16n8k16.row.col.f32.bf16.bf16.f32 "
                 "{%0,%1,%2,%3}, {%4,%5,%6,%7}, {%8,%9}, {%0,%1,%2,%3};"
                 : "+f"(c[0]), "+f"(c[1]), "+f"(c[2]), "+f"(c[3])
                 : "r"(a[0]), "r"(a[1]), "r"(a[2]), "r"(a[3]), "r"(b[0]), "r"(b[1]));
}
__device__ __forceinline__ uint32_t phys(int r, int c) {
    return (uint32_t)(r * 128 + ((c ^ (r & 7)) << 4));
}
__device__ __forceinline__ uint32_t phys256(int r, int c) {
    return (uint32_t)(r * 256 + (((c & 7) ^ (r & 7)) << 4) + ((c & 8) << 4));
}
__device__ __forceinline__ void split_pack_h(float a, float b, uint32_t& hi, uint32_t& lo) {
    __half ha = __float2half(a), hb = __float2half(b);
    __half la = __float2half(a - __half2float(ha));
    __half lb = __float2half(b - __half2float(hb));
    __half2 H(ha, hb), L(la, lb);
    hi = *(uint32_t*)&H;
    lo = *(uint32_t*)&L;
}
__device__ __forceinline__ void split_pack_b(float a, float b, uint32_t& hi, uint32_t& lo) {
    __nv_bfloat16 ha = __float2bfloat16(a), hb = __float2bfloat16(b);
    __nv_bfloat16 la = __float2bfloat16(a - __bfloat162float(ha));
    __nv_bfloat16 lb = __float2bfloat16(b - __bfloat162float(hb));
    __nv_bfloat162 H(ha, hb), L(la, lb);
    hi = *(uint32_t*)&H;
    lo = *(uint32_t*)&L;
}

#define STG_BYTES 49152          // per stage: Ah|Al|Bh (gemm) or Kh|Vh|Vl (attn), 16KB each
#define GEMM_SMEM (3 * STG_BYTES)

// ==== fp16 2-term GEMM: C = (Ah+Al)*Bh^T, 3-stage pipe (R10-proven) ====
__global__ __launch_bounds__(256, 1) void gemm_f16x2(
    const __half* __restrict__ Ahi, const __half* __restrict__ Alo,
    const __half* __restrict__ Bhi, float* __restrict__ C, int N) {
    extern __shared__ char smem[];
    const uint32_t sb = smem_u32(smem);
    const int tid = threadIdx.x, wid = tid >> 5, lane = tid & 31;
    const int m0 = blockIdx.y * 128, n0 = blockIdx.x * 128;
    const int NKI = KK_ / 64;    // 32 iters

    const __half* ah = Ahi + (size_t)m0 * KK_;
    const __half* al = Alo + (size_t)m0 * KK_;
    const __half* bh = Bhi + (size_t)n0 * KK_;

    auto load_stage = [&](int st, int it) {
        const uint32_t base = sb + st * STG_BYTES;
        const int k0 = it * 64;
        for (int q = tid; q < 3072; q += 256) {
            int reg = q >> 10, qq = q & 1023;
            int r = qq >> 3, c = qq & 7;
            const __half* src = (reg == 0) ? ah : (reg == 1) ? al : bh;
            cp16(base + reg * 16384 + phys(r, c), src + (size_t)r * KK_ + k0 + c * 8);
        }
        asm volatile("cp.async.commit_group;" ::: "memory");
    };

    load_stage(0, 0);
    load_stage(1, 1);
    load_stage(2, 2);

    const int wm = (wid & 3) * 32;
    const int wn = (wid >> 2) * 64;
    float acc[2][8][4];
#pragma unroll
    for (int i = 0; i < 2; i++)
#pragma unroll
        for (int j = 0; j < 8; j++)
#pragma unroll
            for (int q = 0; q < 4; q++) acc[i][j][q] = 0.0f;

    const int fr = (lane & 7) + ((lane >> 3) & 1) * 8;
    const int fc = lane >> 4;

    for (int i = 0; i < NKI; i++) {
        if (i < NKI - 2)       asm volatile("cp.async.wait_group 2;" ::: "memory");
        else if (i == NKI - 2) asm volatile("cp.async.wait_group 1;" ::: "memory");
        else                   asm volatile("cp.async.wait_group 0;" ::: "memory");
        __syncthreads();

        const int st = i % 3;
        const uint32_t bA = sb + st * STG_BYTES;
        const uint32_t bAl = bA + 16384, bB = bA + 32768;
#pragma unroll
        for (int s = 0; s < 4; s++) {
            uint32_t ahf[2][4], alf[2][4], bhf[8][2];
#pragma unroll
            for (int mi = 0; mi < 2; mi++) {
                int r = wm + mi * 16 + fr;
                uint32_t off = phys(r, s * 2 + fc);
                ldm4(ahf[mi], bA + off);
                ldm4(alf[mi], bAl + off);
            }
#pragma unroll
            for (int ng = 0; ng < 4; ng++) {
                int r = wn + ng * 16 + fr;
                uint32_t off = phys(r, s * 2 + fc);
                uint32_t t[4];
                ldm4(t, bB + off);
                bhf[ng * 2][0] = t[0]; bhf[ng * 2][1] = t[2];
                bhf[ng * 2 + 1][0] = t[1]; bhf[ng * 2 + 1][1] = t[3];
            }
#pragma unroll
            for (int mi = 0; mi < 2; mi++)
#pragma unroll
                for (int n = 0; n < 8; n++) {
                    mma_f16(acc[mi][n], ahf[mi], bhf[n]);
                    mma_f16(acc[mi][n], alf[mi], bhf[n]);
                }
        }
        __syncthreads();
        if (i + 3 < NKI) load_stage(st, i + 3);
    }

#pragma unroll
    for (int mi = 0; mi < 2; mi++) {
        int r0 = m0 + wm + mi * 16 + (lane >> 2);
#pragma unroll
        for (int n = 0; n < 8; n++) {
            int col = n0 + wn + n * 8 + (lane & 3) * 2;
            *(float2*)(C + (size_t)r0 * N + col)       = make_float2(acc[mi][n][0], acc[mi][n][1]);
            *(float2*)(C + (size_t)(r0 + 8) * N + col) = make_float2(acc[mi][n][2], acc[mi][n][3]);
        }
    }
}

// ============ fp32 -> fp16 hi/lo split ============
__global__ __launch_bounds__(256) void split_fp16(const float* __restrict__ x,
                                                  __half* __restrict__ hi,
                                                  __half* __restrict__ lo,
                                                  int n4) {
    int i = blockIdx.x * 256 + threadIdx.x;
    if (i >= n4) return;
    float4 v = ((const float4*)x)[i];
    uint32_t h01, l01, h23, l23;
    split_pack_h(v.x, v.y, h01, l01);
    split_pack_h(v.z, v.w, h23, l23);
    ((uint32_t*)hi)[2 * i]     = h01;
    ((uint32_t*)hi)[2 * i + 1] = h23;
    ((uint32_t*)lo)[2 * i]     = l01;
    ((uint32_t*)lo)[2 * i + 1] = l23;
}

// ============ gate: (octx * sigmoid(gate)) -> fp16 hi/lo ============
__global__ __launch_bounds__(256) void gate_split(const float* __restrict__ qkv,
                                                  const float* __restrict__ octx,
                                                  __half* __restrict__ hi,
                                                  __half* __restrict__ lo) {
    size_t i4 = (size_t)blockIdx.x * blockDim.x + threadIdx.x;
    size_t e = i4 * 4;
    int d = (int)(e % D_);
    int h = (int)((e / D_) % NH_);
    size_t bs = e / (D_ * NH_);
    const float4 gv = *(const float4*)(qkv + bs * NQKV_ + h * (2 * D_) + D_ + d);
    float4 ov = *(const float4*)(octx + e);
    ov.x *= 1.0f / (1.0f + __expf(-gv.x));
    ov.y *= 1.0f / (1.0f + __expf(-gv.y));
    ov.z *= 1.0f / (1.0f + __expf(-gv.z));
    ov.w *= 1.0f / (1.0f + __expf(-gv.w));
    uint32_t h01, l01, h23, l23;
    split_pack_h(ov.x, ov.y, h01, l01);
    split_pack_h(ov.z, ov.w, h23, l23);
    ((uint32_t*)hi)[2 * i4]     = h01;
    ((uint32_t*)hi)[2 * i4 + 1] = h23;
    ((uint32_t*)lo)[2 * i4]     = l01;
    ((uint32_t*)lo)[2 * i4 + 1] = l23;
}

// ============ W[K,N] fp32 -> Wt fp16 [N,K] (round only) ============
__global__ __launch_bounds__(256) void transpose_half(const float* __restrict__ W,
                                                      __half* __restrict__ thi,
                                                      int N) {
    __shared__ float t[32][33];
    const int n0 = blockIdx.x * 32, k0 = blockIdx.y * 32;
    const int tx = threadIdx.x, ty = threadIdx.y;
    for (int i = ty; i < 32; i += 8)
        t[i][tx] = W[(size_t)(k0 + i) * N + n0 + tx];
    __syncthreads();
    for (int i = ty; i < 32; i += 8)
        thi[(size_t)(n0 + i) * KK_ + k0 + tx] = __float2half(t[tx][i]);
}

// ============ V (cols [4608,5120) of qkv) -> V^T bf16 hi/lo (b,kh,d,s) ========
__global__ __launch_bounds__(256) void v_trans_split(const float* __restrict__ qkv,
                                                     __nv_bfloat16* __restrict__ vth,
                                                     __nv_bfloat16* __restrict__ vtl) {
    __shared__ float t[32][33];
    const int bk = blockIdx.z;
    const int b = bk >> 2, kv = bk & 3;
    const int s0 = blockIdx.x * 32, d0 = blockIdx.y * 32;
    const int tx = threadIdx.x, ty = threadIdx.y;
    for (int i = ty; i < 32; i += 8)
        t[i][tx] = qkv[(size_t)(b * S_ + s0 + i) * NQKV_ + 4608 + kv * D_ + d0 + tx];
    __syncthreads();
    for (int i = ty; i < 32; i += 8) {
        float val = t[tx][i];
        __nv_bfloat16 h = __float2bfloat16(val);
        __nv_bfloat16 l = __float2bfloat16(val - __bfloat162float(h));
        size_t o = ((size_t)(b * NKV_ + kv) * D_ + d0 + i) * S_ + s0 + tx;
        vth[o] = h;
        vtl[o] = l;
    }
}

// ---------------- RMSNorm + RoPE ----------------
__global__ __launch_bounds__(128) void norm_rope_q_h(const float* __restrict__ qkv,
                                                     const float* __restrict__ cosb,
                                                     const float* __restrict__ sinb,
                                                     const float* __restrict__ w,
                                                     __half* __restrict__ qh,
                                                     __half* __restrict__ ql) {
    const int idx = blockIdx.x;
    const int h = idx % NH_;
    const int bs = idx / NH_;
    const int d = threadIdx.x;
    const float* x = qkv + (size_t)bs * NQKV_ + h * (2 * D_);
    float xv = x[d];
    float sq = xv * xv;
#pragma unroll
    for (int o = 16; o > 0; o >>= 1) sq += __shfl_xor_sync(0xffffffffu, sq, o);
    __shared__ float wsum[4];
    __shared__ float xs[D_];
    if ((d & 31) == 0) wsum[d >> 5] = sq;
    __syncthreads();
    float total = wsum[0] + wsum[1] + wsum[2] + wsum[3];
    float xn = xv * rsqrtf(total * (1.0f / D_) + EPS_) * (1.0f + w[d]);
    xs[d] = xn;
    __syncthreads();
    float c = cosb[(size_t)bs * D_ + d];
    float sn = sinb[(size_t)bs * D_ + d];
    float rot = (d < D_ / 2) ? -xs[d + D_ / 2] : xs[d - D_ / 2];
    float val = xn * c + rot * sn;
    const int b = bs / S_, s = bs % S_;
    size_t o = (((size_t)b * NH_ + h) * S_ + s) * D_ + d;
    __half hi = __float2half(val);
    qh[o] = hi;
    ql[o] = __float2half(val - __half2float(hi));
}

__global__ __launch_bounds__(128) void norm_rope_k_h(const float* __restrict__ qkv,
                                                     const float* __restrict__ cosb,
                                                     const float* __restrict__ sinb,
                                                     const float* __restrict__ w,
                                                     __half* __restrict__ kh) {
    const int idx = blockIdx.x;
    const int kv = idx % NKV_;
    const int bs = idx / NKV_;
    const int d = threadIdx.x;
    const float* x = qkv + (size_t)bs * NQKV_ + 4096 + kv * D_;
    float xv = x[d];
    float sq = xv * xv;
#pragma unroll
    for (int o = 16; o > 0; o >>= 1) sq += __shfl_xor_sync(0xffffffffu, sq, o);
    __shared__ float wsum[4];
    __shared__ float xs[D_];
    if ((d & 31) == 0) wsum[d >> 5] = sq;
    __syncthreads();
    float total = wsum[0] + wsum[1] + wsum[2] + wsum[3];
    float xn = xv * rsqrtf(total * (1.0f / D_) + EPS_) * (1.0f + w[d]);
    xs[d] = xn;
    __syncthreads();
    float c = cosb[(size_t)bs * D_ + d];
    float sn = sinb[(size_t)bs * D_ + d];
    float rot = (d < D_ / 2) ? -xs[d + D_ / 2] : xs[d - D_ / 2];
    float val = xn * c + rot * sn;
    const int b = bs / S_, s = bs % S_;
    kh[(((size_t)b * NKV_ + kv) * S_ + s) * D_ + d] = __float2half(val);
}

// ===== single-pass fused attention: QK fp16x2 (Q hi/lo, K hi), PV bf16x3 =====
// smem: Q hi/lo 64KB + 2 stages of (Kh fp16 16KB; Vh,Vl bf16 32KB) = 160KB
#define P2_SMEM 163840
__global__ __launch_bounds__(256, 1) void attn_fused(
    const __half* __restrict__ qh, const __half* __restrict__ ql,
    const __half* __restrict__ khb,
    const __nv_bfloat16* __restrict__ vth, const __nv_bfloat16* __restrict__ vtl,
    float* __restrict__ rowsum,
    float* __restrict__ P, float* __restrict__ octx) {
    extern __shared__ char smem[];
    const uint32_t sb = smem_u32(smem);
    const int tid = threadIdx.x, wid = tid >> 5, lane = tid & 31;
    const int qt = blockIdx.x, bh = blockIdx.y;
    const int b = bh >> 4, h = bh & 15, kv = h >> 2;
    const int q0 = qt * 128;
    const int nk = 2 * qt + 2;
    const __half* qhp = qh + ((size_t)(b * NH_ + h) * S_ + q0) * D_;
    const __half* qlp = ql + ((size_t)(b * NH_ + h) * S_ + q0) * D_;
    const __half* khp = khb + (size_t)(b * NKV_ + kv) * S_ * D_;
    const __nv_bfloat16* vhp = vth + (size_t)(b * NKV_ + kv) * D_ * S_;
    const __nv_bfloat16* vlp = vtl + (size_t)(b * NKV_ + kv) * D_ * S_;

    for (int q = tid; q < 2048; q += 256) {
        int r = q >> 4, c = q & 15;
        uint32_t off = phys256(r, c);
        cp16(sb + off, qhp + (size_t)r * D_ + c * 8);
        cp16(sb + 32768 + off, qlp + (size_t)r * D_ + c * 8);
    }
    auto load_stage = [&](int st, int kt) {
        uint32_t base = sb + 65536 + st * STG_BYTES;
        const __half* sh = khp + (size_t)kt * 64 * D_;
        for (int q = tid; q < 1024; q += 256) {
            int r = q >> 4, c = q & 15;
            cp16(base + phys256(r, c), sh + (size_t)r * D_ + c * 8);
        }
        for (int q = tid; q < 1024; q += 256) {
            int r = q >> 3, c = q & 7;
            uint32_t off = phys(r, c);
            cp16(base + 16384 + off, vhp + (size_t)r * S_ + kt * 64 + c * 8);
            cp16(base + 32768 + off, vlp + (size_t)r * S_ + kt * 64 + c * 8);
        }
    };
    load_stage(0, 0);
    asm volatile("cp.async.commit_group;" ::: "memory");
    load_stage(1, 1);
    asm volatile("cp.async.commit_group;" ::: "memory");

    const int wm = (wid & 3) * 32, wn = (wid >> 2) * 32;
    const int fr = (lane & 7) + ((lane >> 3) & 1) * 8;
    const int fc = lane >> 4;

    float lsum[4] = {0.0f, 0.0f, 0.0f, 0.0f};
    float pv[2][16][4];
#pragma unroll
    for (int mi = 0; mi < 2; mi++)
#pragma unroll
        for (int n = 0; n < 16; n++)
#pragma unroll
            for (int q = 0; q < 4; q++) pv[mi][n][q] = 0.0f;

    for (int kt = 0; kt < nk; kt++) {
        if (kt == nk - 1) asm volatile("cp.async.wait_group 0;" ::: "memory");
        else              asm volatile("cp.async.wait_group 1;" ::: "memory");
        __syncthreads();
        const uint32_t stg = sb + 65536 + (kt & 1) * STG_BYTES;
        const uint32_t bK = stg, bV = stg + 16384, bVl = stg + 32768;

        float acc[2][4][4];
#pragma unroll
        for (int i = 0; i < 2; i++)
#pragma unroll
            for (int j = 0; j < 4; j++)
#pragma unroll
                for (int q = 0; q < 4; q++) acc[i][j][q] = 0.0f;

#pragma unroll
        for (int ks = 0; ks < 8; ks++) {
            uint32_t ahf[2][4], alf[2][4], bhf[4][2];
#pragma unroll
            for (int mi = 0; mi < 2; mi++) {
                uint32_t off = phys256(wm + mi * 16 + fr, ks * 2 + fc);
                ldm4(ahf[mi], sb + off);
                ldm4(alf[mi], sb + 32768 + off);
            }
#pragma unroll
            for (int ng = 0; ng < 2; ng++) {
                uint32_t off = phys256(wn + ng * 16 + fr, ks * 2 + fc);
                uint32_t t[4];
                ldm4(t, bK + off);
                bhf[ng * 2][0] = t[0]; bhf[ng * 2][1] = t[2];
                bhf[ng * 2 + 1][0] = t[1]; bhf[ng * 2 + 1][1] = t[3];
            }
#pragma unroll
            for (int mi = 0; mi < 2; mi++)
#pragma unroll
                for (int n = 0; n < 4; n++) {
                    mma_f16(acc[mi][n], ahf[mi], bhf[n]);
                    mma_f16(acc[mi][n], alf[mi], bhf[n]);
                }
        }

        // e = exp(s*SCALE - MAXB)  (masked -> 0); accumulate rowsum; write P
        const bool full = (kt * 64 + 63 <= q0);
#pragma unroll
        for (int mi = 0; mi < 2; mi++)
#pragma unroll
            for (int n = 0; n < 4; n++)
#pragma unroll
                for (int e = 0; e < 4; e++) {
                    const int slot = mi * 2 + (e >> 1);
                    float p = __expf(acc[mi][n][e] * SCALE_ - MAXB_);
                    if (!full) {
                        int gi = q0 + wm + mi * 16 + (lane >> 2) + (e >> 1) * 8;
                        int gj = kt * 64 + wn + n * 8 + (lane & 3) * 2 + (e & 1);
                        if (gj > gi) p = 0.0f;
                    }
                    acc[mi][n][e] = p;
                    lsum[slot] += p;
                }
#pragma unroll
        for (int mi = 0; mi < 2; mi++) {
            int r0 = q0 + wm + mi * 16 + (lane >> 2);
#pragma unroll
            for (int n = 0; n < 4; n++) {
                int col = kt * 64 + wn + n * 8 + (lane & 3) * 2;
                *(float2*)(P + ((size_t)bh * S_ + r0) * S_ + col) =
                    make_float2(acc[mi][n][0], acc[mi][n][1]);
                *(float2*)(P + ((size_t)bh * S_ + r0 + 8) * S_ + col) =
                    make_float2(acc[mi][n][2], acc[mi][n][3]);
            }
        }

        // PV: e (A frags, bf16 hi/lo) x V^T (B frags, bf16 hi/lo), 3-term
#pragma unroll
        for (int ksl = 0; ksl < 2; ksl++) {
            uint32_t pah[2][4], pal[2][4];
#pragma unroll
            for (int mi = 0; mi < 2; mi++) {
                const int n0 = ksl * 2, n1 = ksl * 2 + 1;
                split_pack_b(acc[mi][n0][0], acc[mi][n0][1], pah[mi][0], pal[mi][0]);
                split_pack_b(acc[mi][n0][2], acc[mi][n0][3], pah[mi][1], pal[mi][1]);
                split_pack_b(acc[mi][n1][0], acc[mi][n1][1], pah[mi][2], pal[mi][2]);
                split_pack_b(acc[mi][n1][2], acc[mi][n1][3], pah[mi][3], pal[mi][3]);
            }
            const int cc = (wn >> 3) + ksl * 2;
#pragma unroll
            for (int dg = 0; dg < 8; dg++) {
                uint32_t t[4], bh2[2][2], bl2[2][2];
                ldm4(t, bV + phys(dg * 16 + fr, cc + fc));
                bh2[0][0] = t[0]; bh2[0][1] = t[2];
                bh2[1][0] = t[1]; bh2[1][1] = t[3];
                ldm4(t, bVl + phys(dg * 16 + fr, cc + fc));
                bl2[0][0] = t[0]; bl2[0][1] = t[2];
                bl2[1][0] = t[1]; bl2[1][1] = t[3];
#pragma unroll
                for (int mi = 0; mi < 2; mi++)
#pragma unroll
                    for (int sub = 0; sub < 2; sub++) {
                        const int nf = dg * 2 + sub;
                        mma_bf16(pv[mi][nf], pah[mi], bh2[sub]);
                        mma_bf16(pv[mi][nf], pah[mi], bl2[sub]);
                        mma_bf16(pv[mi][nf], pal[mi], bh2[sub]);
                    }
            }
        }
        __syncthreads();
        if (kt + 2 < nk) {
            load_stage(kt & 1, kt + 2);
            asm volatile("cp.async.commit_group;" ::: "memory");
        }
    }

    // reduce lsum across the 4 lanes of each quad
#pragma unroll
    for (int o = 1; o < 4; o <<= 1)
#pragma unroll
        for (int slot = 0; slot < 4; slot++)
            lsum[slot] += __shfl_xor_sync(0xffffffffu, lsum[slot], o);

    // combine the two col-warp groups; normalize; store octx + rowsum
    __syncthreads();
    float* ob = (float*)smem;          // 128 rows x pitch 136 floats
    float* lrow = ob + 128 * 136;
    if (wn == 32) {
#pragma unroll
        for (int mi = 0; mi < 2; mi++) {
            int r0 = wm + mi * 16 + (lane >> 2);
#pragma unroll
            for (int nf = 0; nf < 16; nf++) {
                int d = nf * 8 + (lane & 3) * 2;
                *(float2*)&ob[(size_t)r0 * 136 + d]       = make_float2(pv[mi][nf][0], pv[mi][nf][1]);
                *(float2*)&ob[(size_t)(r0 + 8) * 136 + d] = make_float2(pv[mi][nf][2], pv[mi][nf][3]);
            }
            if ((lane & 3) == 0) {
                lrow[r0]     = lsum[mi * 2];
                lrow[r0 + 8] = lsum[mi * 2 + 1];
            }
        }
    }
    __syncthreads();
    if (wn == 0) {
#pragma unroll
        for (int mi = 0; mi < 2; mi++) {
            int r0 = wm + mi * 16 + (lane >> 2);
            float lt0 = lsum[mi * 2] + lrow[r0];
            float lt1 = lsum[mi * 2 + 1] + lrow[r0 + 8];
            float inv0 = 1.0f / lt0;
            float inv1 = 1.0f / lt1;
            if ((lane & 3) == 0) {
                rowsum[(size_t)bh * S_ + q0 + r0]     = lt0;
                rowsum[(size_t)bh * S_ + q0 + r0 + 8] = lt1;
            }
#pragma unroll
            for (int nf = 0; nf < 16; nf++) {
                int d = nf * 8 + (lane & 3) * 2;
                float2 a0 = *(float2*)&ob[(size_t)r0 * 136 + d];
                float2 a1 = *(float2*)&ob[(size_t)(r0 + 8) * 136 + d];
                float* o0 = octx + ((size_t)(b * S_ + q0 + r0) * NH_ + h) * D_ + d;
                float* o1 = octx + ((size_t)(b * S_ + q0 + r0 + 8) * NH_ + h) * D_ + d;
                *(float2*)o0 = make_float2((pv[mi][nf][0] + a0.x) * inv0, (pv[mi][nf][1] + a0.y) * inv0);
                *(float2*)o1 = make_float2((pv[mi][nf][2] + a1.x) * inv1, (pv[mi][nf][3] + a1.y) * inv1);
            }
        }
    }
}

// -------- fixup: normalize written P region by 1/rowsum, zero the rest --------
__global__ __launch_bounds__(128) void normalize_zero(float* __restrict__ P,
                                                      const float* __restrict__ rowsum) {
    const int row = blockIdx.x;          // bh*S + i
    const int i = row & (S_ - 1);
    const int jend = ((i >> 7) + 1) << 7;
    const float inv = 1.0f / rowsum[row];
    float* p = P + (size_t)row * S_;
    const int t4 = threadIdx.x * 4;
    for (int j = t4; j < jend; j += 512) {
        float4 v = *(float4*)(p + j);
        v.x *= inv; v.y *= inv; v.z *= inv; v.w *= inv;
        *(float4*)(p + j) = v;
    }
    const float4 z = {0, 0, 0, 0};
    for (int j = jend + t4; j < S_; j += 512)
        *(float4*)(p + j) = z;
}

// ---------------- launch (graph-capturable fork/join on a side stream) --------
extern "C" void kernel_launch(void* const* d_in, const int* in_sizes, int n_in,
                              void* d_out, int out_size) {
    const float* hidden = (const float*)d_in[0];
    const float* cosb   = (const float*)d_in[1];
    const float* sinb   = (const float*)d_in[2];
    const float* Wq     = (const float*)d_in[4];
    const float* Wk     = (const float*)d_in[5];
    const float* Wv     = (const float*)d_in[6];
    const float* Wo     = (const float*)d_in[7];
    const float* qnw    = (const float*)d_in[8];
    const float* knw    = (const float*)d_in[9];

    float* out = (float*)d_out;
    const size_t ao_elems = (size_t)MT_ * HID_;
    float* P = out + ao_elems;

    float *qkv, *octx, *rsum;
    __half *ahi, *alo, *wqh, *woh, *ohi, *olo, *qhv, *qlv, *khv;
    __nv_bfloat16 *vth, *vtl;
    cudaGetSymbolAddress((void**)&qkv,  g_qkv);
    cudaGetSymbolAddress((void**)&octx, g_octx);
    cudaGetSymbolAddress((void**)&rsum, g_rowsum);
    cudaGetSymbolAddress((void**)&ahi,  g_ahi);
    cudaGetSymbolAddress((void**)&alo,  g_alo);
    cudaGetSymbolAddress((void**)&wqh,  g_wqkvh);
    cudaGetSymbolAddress((void**)&woh,  g_woh);
    cudaGetSymbolAddress((void**)&ohi,  g_ohi);
    cudaGetSymbolAddress((void**)&olo,  g_olo);
    cudaGetSymbolAddress((void**)&qhv,  g_qh);
    cudaGetSymbolAddress((void**)&qlv,  g_ql);
    cudaGetSymbolAddress((void**)&khv,  g_kh);
    cudaGetSymbolAddress((void**)&vth,  g_vth);
    cudaGetSymbolAddress((void**)&vtl,  g_vtl);

    cudaFuncSetAttribute(gemm_f16x2, cudaFuncAttributeMaxDynamicSharedMemorySize, GEMM_SMEM);
    cudaFuncSetAttribute(attn_fused, cudaFuncAttributeMaxDynamicSharedMemorySize, P2_SMEM);

    cudaStream_t s2;
    cudaStreamCreate(&s2);
    cudaEvent_t e1, e2, e3, e4, e5, e6;
    cudaEventCreateWithFlags(&e1, cudaEventDisableTiming);
    cudaEventCreateWithFlags(&e2, cudaEventDisableTiming);
    cudaEventCreateWithFlags(&e3, cudaEventDisableTiming);
    cudaEventCreateWithFlags(&e4, cudaEventDisableTiming);
    cudaEventCreateWithFlags(&e5, cudaEventDisableTiming);
    cudaEventCreateWithFlags(&e6, cudaEventDisableTiming);

    // ---- fork 1: weight transposes (s2) || hidden split (default) ----
    cudaEventRecord(e1, 0);
    cudaStreamWaitEvent(s2, e1, 0);
    transpose_half<<<dim3(4096 / 32, KK_ / 32), dim3(32, 8), 0, s2>>>(Wq, wqh, 4096);
    transpose_half<<<dim3(512 / 32,  KK_ / 32), dim3(32, 8), 0, s2>>>(Wk, wqh + (size_t)4096 * KK_, 512);
    transpose_half<<<dim3(512 / 32,  KK_ / 32), dim3(32, 8), 0, s2>>>(Wv, wqh + (size_t)4608 * KK_, 512);
    transpose_half<<<dim3(2048 / 32, KK_ / 32), dim3(32, 8), 0, s2>>>(Wo, woh, 2048);
    cudaEventRecord(e2, s2);
    {
        int n4 = (int)((size_t)MT_ * KK_ / 4);
        split_fp16<<<(n4 + 255) / 256, 256>>>(hidden, ahi, alo, n4);
    }
    cudaStreamWaitEvent(0, e2, 0);

    // fused QKV projection (fp16 2-term)
    gemm_f16x2<<<dim3(NQKV_ / 128, MT_ / 128), 256, GEMM_SMEM>>>(ahi, alo, wqh, qkv, NQKV_);

    // ---- fork 2: norm_k + v_trans (s2) || norm_q (default) ----
    cudaEventRecord(e3, 0);
    cudaStreamWaitEvent(s2, e3, 0);
    norm_rope_k_h<<<B_ * S_ * NKV_, 128, 0, s2>>>(qkv, cosb, sinb, knw, khv);
    v_trans_split<<<dim3(S_ / 32, D_ / 32, B_ * NKV_), dim3(32, 8), 0, s2>>>(qkv, vth, vtl);
    cudaEventRecord(e4, s2);
    norm_rope_q_h<<<B_ * S_ * NH_, 128>>>(qkv, cosb, sinb, qnw, qhv, qlv);
    cudaStreamWaitEvent(0, e4, 0);

    // fused single-pass attention
    attn_fused<<<dim3(S_ / 128, B_ * NH_), 256, P2_SMEM>>>(qhv, qlv, khv, vth, vtl,
                                                           rsum, P, octx);

    // ---- fork 3: P normalize/zero (s2) || gate + Wo GEMM (default) ----
    cudaEventRecord(e5, 0);
    cudaStreamWaitEvent(s2, e5, 0);
    normalize_zero<<<B_ * NH_ * S_, 128, 0, s2>>>(P, rsum);
    cudaEventRecord(e6, s2);
    gate_split<<<(int)(((size_t)MT_ * 2048 / 4) / 256), 256>>>(qkv, octx, ohi, olo);
    gemm_f16x2<<<dim3(2048 / 128, MT_ / 128), 256, GEMM_SMEM>>>(ohi, olo, woh, out, 2048);
    cudaStreamWaitEvent(0, e6, 0);

    cudaEventDestroy(e1); cudaEventDestroy(e2); cudaEventDestroy(e3);
    cudaEventDestroy(e4); cudaEventDestroy(e5); cudaEventDestroy(e6);
    cudaStreamDestroy(s2);
}

// round 16
// speedup vs baseline: 1.0288x; 1.0027x over previous
#include <cuda_runtime.h>
#include <cuda_fp16.h>
#include <cuda_bf16.h>
#include <cstdint>

#define B_  4
#define S_  2048
#define HID_ 2048
#define NH_ 16
#define NKV_ 4
#define D_  128
#define EPS_ 1e-6f
#define SCALE_ 0.08838834764831845f   // 128^-0.5
#define MAXB_ 11.5f                   // score bound: sqrt(128)*sqrt(128)*SCALE=11.314

#define MT_  8192     // B*S rows
#define KK_  2048     // GEMM K (always HID_)
#define NQKV_ 5120    // fused projection width: 4096 (q,gate) + 512 (k) + 512 (v)

// ---------------- scratch (static __device__, allocation-free) ----------------
__device__ float g_qkv [(size_t)MT_*NQKV_];
__device__ float g_octx[(size_t)MT_*2048];
__device__ float g_rowsum[(size_t)B_*NH_*S_];
__device__ __half g_ahi[(size_t)MT_*KK_],  g_alo[(size_t)MT_*KK_];
__device__ __half g_wqkvh[(size_t)NQKV_*KK_];
__device__ __half g_woh[(size_t)2048*KK_];
__device__ __half g_ohi[(size_t)MT_*2048], g_olo[(size_t)MT_*2048];
__device__ __half g_qh[(size_t)B_*NH_*S_*D_], g_ql[(size_t)B_*NH_*S_*D_];
__device__ __half g_kh[(size_t)B_*NKV_*S_*D_];
__device__ __nv_bfloat16 g_vth[(size_t)B_*NKV_*D_*S_], g_vtl[(size_t)B_*NKV_*D_*S_];

// ================= PTX helpers (family-target-safe: sm_80+ features only) =====
__device__ __forceinline__ uint32_t smem_u32(const void* p) {
    uint32_t a;
    asm("{ .reg .u64 t; cvta.to.shared.u64 t, %1; cvt.u32.u64 %0, t; }" : "=r"(a) : "l"(p));
    return a;
}
__device__ __forceinline__ void cp16(uint32_t s, const void* g) {
    asm volatile("cp.async.cg.shared.global [%0], [%1], 16;" :: "r"(s), "l"(g));
}
__device__ __forceinline__ void ldm4(uint32_t* r, uint32_t addr) {
    asm volatile("ldmatrix.sync.aligned.m8n8.x4.shared.b16 {%0,%1,%2,%3}, [%4];"
                 : "=r"(r[0]), "=r"(r[1]), "=r"(r[2]), "=r"(r[3]) : "r"(addr));
}
__device__ __forceinline__ void mma_f16(float* c, const uint32_t* a, const uint32_t* b) {
    asm volatile("mma.sync.aligned.m16n8k16.row.col.f32.f16.f16.f32 "
                 "{%0,%1,%2,%3}, {%4,%5,%6,%7}, {%8,%9}, {%0,%1,%2,%3};"
                 : "+f"(c[0]), "+f"(c[1]), "+f"(c[2]), "+f"(c[3])
                 : "r"(a[0]), "r"(a[1]), "r"(a[2]), "r"(a[3]), "r"(b[0]), "r"(b[1]));
}
__device__ __forceinline__ void mma_bf16(float* c, const uint32_t* a, const uint32_t* b) {
    asm volatile("mma.sync.aligned.m16n8k16.row.col.f32.bf16.bf16.f32 "
                 "{%0,%1,%2,%3}, {%4,%5,%6,%7}, {%8,%9}, {%0,%1,%2,%3};"
                 : "+f"(c[0]), "+f"(c[1]), "+f"(c[2]), "+f"(c[3])
                 : "r"(a[0]), "r"(a[1]), "r"(a[2]), "r"(a[3]), "r"(b[0]), "r"(b[1]));
}
__device__ __forceinline__ uint32_t phys(int r, int c) {
    return (uint32_t)(r * 128 + ((c ^ (r & 7)) << 4));
}
__device__ __forceinline__ uint32_t phys256(int r, int c) {
    return (uint32_t)(r * 256 + (((c & 7) ^ (r & 7)) << 4) + ((c & 8) << 4));
}
__device__ __forceinline__ void split_pack_h(float a, float b, uint32_t& hi, uint32_t& lo) {
    __half ha = __float2half(a), hb = __float2half(b);
    __half la = __float2half(a - __half2float(ha));
    __half lb = __float2half(b - __half2float(hb));
    __half2 H(ha, hb), L(la, lb);
    hi = *(uint32_t*)&H;
    lo = *(uint32_t*)&L;
}
__device__ __forceinline__ void split_pack_b(float a, float b, uint32_t& hi, uint32_t& lo) {
    __nv_bfloat16 ha = __float2bfloat16(a), hb = __float2bfloat16(b);
    __nv_bfloat16 la = __float2bfloat16(a - __bfloat162float(ha));
    __nv_bfloat16 lb = __float2bfloat16(b - __bfloat162float(hb));
    __nv_bfloat162 H(ha, hb), L(la, lb);
    hi = *(uint32_t*)&H;
    lo = *(uint32_t*)&L;
}

#define STG_BYTES 49152          // per stage: Ah|Al|Bh (gemm) or Kh|Vh|Vl (attn), 16KB each
#define GEMM_SMEM (3 * STG_BYTES)

// ==== fp16 2-term GEMM: C = (Ah+Al)*Bh^T, 3-stage pipe (R10-proven) ====
__global__ __launch_bounds__(256, 1) void gemm_f16x2(
    const __half* __restrict__ Ahi, const __half* __restrict__ Alo,
    const __half* __restrict__ Bhi, float* __restrict__ C, int N) {
    extern __shared__ char smem[];
    const uint32_t sb = smem_u32(smem);
    const int tid = threadIdx.x, wid = tid >> 5, lane = tid & 31;
    const int m0 = blockIdx.y * 128, n0 = blockIdx.x * 128;
    const int NKI = KK_ / 64;    // 32 iters

    const __half* ah = Ahi + (size_t)m0 * KK_;
    const __half* al = Alo + (size_t)m0 * KK_;
    const __half* bh = Bhi + (size_t)n0 * KK_;

    auto load_stage = [&](int st, int it) {
        const uint32_t base = sb + st * STG_BYTES;
        const int k0 = it * 64;
        for (int q = tid; q < 3072; q += 256) {
            int reg = q >> 10, qq = q & 1023;
            int r = qq >> 3, c = qq & 7;
            const __half* src = (reg == 0) ? ah : (reg == 1) ? al : bh;
            cp16(base + reg * 16384 + phys(r, c), src + (size_t)r * KK_ + k0 + c * 8);
        }
        asm volatile("cp.async.commit_group;" ::: "memory");
    };

    load_stage(0, 0);
    load_stage(1, 1);
    load_stage(2, 2);

    const int wm = (wid & 3) * 32;
    const int wn = (wid >> 2) * 64;
    float acc[2][8][4];
#pragma unroll
    for (int i = 0; i < 2; i++)
#pragma unroll
        for (int j = 0; j < 8; j++)
#pragma unroll
            for (int q = 0; q < 4; q++) acc[i][j][q] = 0.0f;

    const int fr = (lane & 7) + ((lane >> 3) & 1) * 8;
    const int fc = lane >> 4;

    for (int i = 0; i < NKI; i++) {
        if (i < NKI - 2)       asm volatile("cp.async.wait_group 2;" ::: "memory");
        else if (i == NKI - 2) asm volatile("cp.async.wait_group 1;" ::: "memory");
        else                   asm volatile("cp.async.wait_group 0;" ::: "memory");
        __syncthreads();

        const int st = i % 3;
        const uint32_t bA = sb + st * STG_BYTES;
        const uint32_t bAl = bA + 16384, bB = bA + 32768;
#pragma unroll
        for (int s = 0; s < 4; s++) {
            uint32_t ahf[2][4], alf[2][4], bhf[8][2];
#pragma unroll
            for (int mi = 0; mi < 2; mi++) {
                int r = wm + mi * 16 + fr;
                uint32_t off = phys(r, s * 2 + fc);
                ldm4(ahf[mi], bA + off);
                ldm4(alf[mi], bAl + off);
            }
#pragma unroll
            for (int ng = 0; ng < 4; ng++) {
                int r = wn + ng * 16 + fr;
                uint32_t off = phys(r, s * 2 + fc);
                uint32_t t[4];
                ldm4(t, bB + off);
                bhf[ng * 2][0] = t[0]; bhf[ng * 2][1] = t[2];
                bhf[ng * 2 + 1][0] = t[1]; bhf[ng * 2 + 1][1] = t[3];
            }
#pragma unroll
            for (int mi = 0; mi < 2; mi++)
#pragma unroll
                for (int n = 0; n < 8; n++) {
                    mma_f16(acc[mi][n], ahf[mi], bhf[n]);
                    mma_f16(acc[mi][n], alf[mi], bhf[n]);
                }
        }
        __syncthreads();
        if (i + 3 < NKI) load_stage(st, i + 3);
    }

#pragma unroll
    for (int mi = 0; mi < 2; mi++) {
        int r0 = m0 + wm + mi * 16 + (lane >> 2);
#pragma unroll
        for (int n = 0; n < 8; n++) {
            int col = n0 + wn + n * 8 + (lane & 3) * 2;
            *(float2*)(C + (size_t)r0 * N + col)       = make_float2(acc[mi][n][0], acc[mi][n][1]);
            *(float2*)(C + (size_t)(r0 + 8) * N + col) = make_float2(acc[mi][n][2], acc[mi][n][3]);
        }
    }
}

// ============ fp32 -> fp16 hi/lo split ============
__global__ __launch_bounds__(256) void split_fp16(const float* __restrict__ x,
                                                  __half* __restrict__ hi,
                                                  __half* __restrict__ lo,
                                                  int n4) {
    int i = blockIdx.x * 256 + threadIdx.x;
    if (i >= n4) return;
    float4 v = ((const float4*)x)[i];
    uint32_t h01, l01, h23, l23;
    split_pack_h(v.x, v.y, h01, l01);
    split_pack_h(v.z, v.w, h23, l23);
    ((uint32_t*)hi)[2 * i]     = h01;
    ((uint32_t*)hi)[2 * i + 1] = h23;
    ((uint32_t*)lo)[2 * i]     = l01;
    ((uint32_t*)lo)[2 * i + 1] = l23;
}

// ============ gate: (octx * sigmoid(gate)) -> fp16 hi/lo ============
__global__ __launch_bounds__(256) void gate_split(const float* __restrict__ qkv,
                                                  const float* __restrict__ octx,
                                                  __half* __restrict__ hi,
                                                  __half* __restrict__ lo) {
    size_t i4 = (size_t)blockIdx.x * blockDim.x + threadIdx.x;
    size_t e = i4 * 4;
    int d = (int)(e % D_);
    int h = (int)((e / D_) % NH_);
    size_t bs = e / (D_ * NH_);
    const float4 gv = *(const float4*)(qkv + bs * NQKV_ + h * (2 * D_) + D_ + d);
    float4 ov = *(const float4*)(octx + e);
    ov.x *= 1.0f / (1.0f + __expf(-gv.x));
    ov.y *= 1.0f / (1.0f + __expf(-gv.y));
    ov.z *= 1.0f / (1.0f + __expf(-gv.z));
    ov.w *= 1.0f / (1.0f + __expf(-gv.w));
    uint32_t h01, l01, h23, l23;
    split_pack_h(ov.x, ov.y, h01, l01);
    split_pack_h(ov.z, ov.w, h23, l23);
    ((uint32_t*)hi)[2 * i4]     = h01;
    ((uint32_t*)hi)[2 * i4 + 1] = h23;
    ((uint32_t*)lo)[2 * i4]     = l01;
    ((uint32_t*)lo)[2 * i4 + 1] = l23;
}

// ============ W[K,N] fp32 -> Wt fp16 [N,K] (round only) ============
__global__ __launch_bounds__(256) void transpose_half(const float* __restrict__ W,
                                                      __half* __restrict__ thi,
                                                      int N) {
    __shared__ float t[32][33];
    const int n0 = blockIdx.x * 32, k0 = blockIdx.y * 32;
    const int tx = threadIdx.x, ty = threadIdx.y;
    for (int i = ty; i < 32; i += 8)
        t[i][tx] = W[(size_t)(k0 + i) * N + n0 + tx];
    __syncthreads();
    for (int i = ty; i < 32; i += 8)
        thi[(size_t)(n0 + i) * KK_ + k0 + tx] = __float2half(t[tx][i]);
}

// ============ V (cols [4608,5120) of qkv) -> V^T bf16 hi/lo (b,kh,d,s) ========
__global__ __launch_bounds__(256) void v_trans_split(const float* __restrict__ qkv,
                                                     __nv_bfloat16* __restrict__ vth,
                                                     __nv_bfloat16* __restrict__ vtl) {
    __shared__ float t[32][33];
    const int bk = blockIdx.z;
    const int b = bk >> 2, kv = bk & 3;
    const int s0 = blockIdx.x * 32, d0 = blockIdx.y * 32;
    const int tx = threadIdx.x, ty = threadIdx.y;
    for (int i = ty; i < 32; i += 8)
        t[i][tx] = qkv[(size_t)(b * S_ + s0 + i) * NQKV_ + 4608 + kv * D_ + d0 + tx];
    __syncthreads();
    for (int i = ty; i < 32; i += 8) {
        float val = t[tx][i];
        __nv_bfloat16 h = __float2bfloat16(val);
        __nv_bfloat16 l = __float2bfloat16(val - __bfloat162float(h));
        size_t o = ((size_t)(b * NKV_ + kv) * D_ + d0 + i) * S_ + s0 + tx;
        vth[o] = h;
        vtl[o] = l;
    }
}

// ---------------- RMSNorm + RoPE ----------------
__global__ __launch_bounds__(128) void norm_rope_q_h(const float* __restrict__ qkv,
                                                     const float* __restrict__ cosb,
                                                     const float* __restrict__ sinb,
                                                     const float* __restrict__ w,
                                                     __half* __restrict__ qh,
                                                     __half* __restrict__ ql) {
    const int idx = blockIdx.x;
    const int h = idx % NH_;
    const int bs = idx / NH_;
    const int d = threadIdx.x;
    const float* x = qkv + (size_t)bs * NQKV_ + h * (2 * D_);
    float xv = x[d];
    float sq = xv * xv;
#pragma unroll
    for (int o = 16; o > 0; o >>= 1) sq += __shfl_xor_sync(0xffffffffu, sq, o);
    __shared__ float wsum[4];
    __shared__ float xs[D_];
    if ((d & 31) == 0) wsum[d >> 5] = sq;
    __syncthreads();
    float total = wsum[0] + wsum[1] + wsum[2] + wsum[3];
    float xn = xv * rsqrtf(total * (1.0f / D_) + EPS_) * (1.0f + w[d]);
    xs[d] = xn;
    __syncthreads();
    float c = cosb[(size_t)bs * D_ + d];
    float sn = sinb[(size_t)bs * D_ + d];
    float rot = (d < D_ / 2) ? -xs[d + D_ / 2] : xs[d - D_ / 2];
    float val = xn * c + rot * sn;
    const int b = bs / S_, s = bs % S_;
    size_t o = (((size_t)b * NH_ + h) * S_ + s) * D_ + d;
    __half hi = __float2half(val);
    qh[o] = hi;
    ql[o] = __float2half(val - __half2float(hi));
}

__global__ __launch_bounds__(128) void norm_rope_k_h(const float* __restrict__ qkv,
                                                     const float* __restrict__ cosb,
                                                     const float* __restrict__ sinb,
                                                     const float* __restrict__ w,
                                                     __half* __restrict__ kh) {
    const int idx = blockIdx.x;
    const int kv = idx % NKV_;
    const int bs = idx / NKV_;
    const int d = threadIdx.x;
    const float* x = qkv + (size_t)bs * NQKV_ + 4096 + kv * D_;
    float xv = x[d];
    float sq = xv * xv;
#pragma unroll
    for (int o = 16; o > 0; o >>= 1) sq += __shfl_xor_sync(0xffffffffu, sq, o);
    __shared__ float wsum[4];
    __shared__ float xs[D_];
    if ((d & 31) == 0) wsum[d >> 5] = sq;
    __syncthreads();
    float total = wsum[0] + wsum[1] + wsum[2] + wsum[3];
    float xn = xv * rsqrtf(total * (1.0f / D_) + EPS_) * (1.0f + w[d]);
    xs[d] = xn;
    __syncthreads();
    float c = cosb[(size_t)bs * D_ + d];
    float sn = sinb[(size_t)bs * D_ + d];
    float rot = (d < D_ / 2) ? -xs[d + D_ / 2] : xs[d - D_ / 2];
    float val = xn * c + rot * sn;
    const int b = bs / S_, s = bs % S_;
    kh[(((size_t)b * NKV_ + kv) * S_ + s) * D_ + d] = __float2half(val);
}

// ===== single-pass fused attention: QK fp16x2 (Q hi/lo, K hi), PV bf16x3 =====
// heavy CTAs (large qt) launch first: qt = gridDim.x-1-blockIdx.x
// smem: Q hi/lo 64KB + 2 stages of (Kh fp16 16KB; Vh,Vl bf16 32KB) = 160KB
#define P2_SMEM 163840
__global__ __launch_bounds__(256, 1) void attn_fused(
    const __half* __restrict__ qh, const __half* __restrict__ ql,
    const __half* __restrict__ khb,
    const __nv_bfloat16* __restrict__ vth, const __nv_bfloat16* __restrict__ vtl,
    float* __restrict__ rowsum,
    float* __restrict__ P, float* __restrict__ octx) {
    extern __shared__ char smem[];
    const uint32_t sb = smem_u32(smem);
    const int tid = threadIdx.x, wid = tid >> 5, lane = tid & 31;
    const int qt = (int)gridDim.x - 1 - (int)blockIdx.x;   // heavy CTAs first
    const int bh = blockIdx.y;
    const int b = bh >> 4, h = bh & 15, kv = h >> 2;
    const int q0 = qt * 128;
    const int nk = 2 * qt + 2;
    const __half* qhp = qh + ((size_t)(b * NH_ + h) * S_ + q0) * D_;
    const __half* qlp = ql + ((size_t)(b * NH_ + h) * S_ + q0) * D_;
    const __half* khp = khb + (size_t)(b * NKV_ + kv) * S_ * D_;
    const __nv_bfloat16* vhp = vth + (size_t)(b * NKV_ + kv) * D_ * S_;
    const __nv_bfloat16* vlp = vtl + (size_t)(b * NKV_ + kv) * D_ * S_;

    for (int q = tid; q < 2048; q += 256) {
        int r = q >> 4, c = q & 15;
        uint32_t off = phys256(r, c);
        cp16(sb + off, qhp + (size_t)r * D_ + c * 8);
        cp16(sb + 32768 + off, qlp + (size_t)r * D_ + c * 8);
    }
    auto load_stage = [&](int st, int kt) {
        uint32_t base = sb + 65536 + st * STG_BYTES;
        const __half* sh = khp + (size_t)kt * 64 * D_;
        for (int q = tid; q < 1024; q += 256) {
            int r = q >> 4, c = q & 15;
            cp16(base + phys256(r, c), sh + (size_t)r * D_ + c * 8);
        }
        for (int q = tid; q < 1024; q += 256) {
            int r = q >> 3, c = q & 7;
            uint32_t off = phys(r, c);
            cp16(base + 16384 + off, vhp + (size_t)r * S_ + kt * 64 + c * 8);
            cp16(base + 32768 + off, vlp + (size_t)r * S_ + kt * 64 + c * 8);
        }
    };
    load_stage(0, 0);
    asm volatile("cp.async.commit_group;" ::: "memory");
    load_stage(1, 1);
    asm volatile("cp.async.commit_group;" ::: "memory");

    const int wm = (wid & 3) * 32, wn = (wid >> 2) * 32;
    const int fr = (lane & 7) + ((lane >> 3) & 1) * 8;
    const int fc = lane >> 4;

    float lsum[4] = {0.0f, 0.0f, 0.0f, 0.0f};
    float pv[2][16][4];
#pragma unroll
    for (int mi = 0; mi < 2; mi++)
#pragma unroll
        for (int n = 0; n < 16; n++)
#pragma unroll
            for (int q = 0; q < 4; q++) pv[mi][n][q] = 0.0f;

    for (int kt = 0; kt < nk; kt++) {
        if (kt == nk - 1) asm volatile("cp.async.wait_group 0;" ::: "memory");
        else              asm volatile("cp.async.wait_group 1;" ::: "memory");
        __syncthreads();
        const uint32_t stg = sb + 65536 + (kt & 1) * STG_BYTES;
        const uint32_t bK = stg, bV = stg + 16384, bVl = stg + 32768;

        float acc[2][4][4];
#pragma unroll
        for (int i = 0; i < 2; i++)
#pragma unroll
            for (int j = 0; j < 4; j++)
#pragma unroll
                for (int q = 0; q < 4; q++) acc[i][j][q] = 0.0f;

#pragma unroll
        for (int ks = 0; ks < 8; ks++) {
            uint32_t ahf[2][4], alf[2][4], bhf[4][2];
#pragma unroll
            for (int mi = 0; mi < 2; mi++) {
                uint32_t off = phys256(wm + mi * 16 + fr, ks * 2 + fc);
                ldm4(ahf[mi], sb + off);
                ldm4(alf[mi], sb + 32768 + off);
            }
#pragma unroll
            for (int ng = 0; ng < 2; ng++) {
                uint32_t off = phys256(wn + ng * 16 + fr, ks * 2 + fc);
                uint32_t t[4];
                ldm4(t, bK + off);
                bhf[ng * 2][0] = t[0]; bhf[ng * 2][1] = t[2];
                bhf[ng * 2 + 1][0] = t[1]; bhf[ng * 2 + 1][1] = t[3];
            }
#pragma unroll
            for (int mi = 0; mi < 2; mi++)
#pragma unroll
                for (int n = 0; n < 4; n++) {
                    mma_f16(acc[mi][n], ahf[mi], bhf[n]);
                    mma_f16(acc[mi][n], alf[mi], bhf[n]);
                }
        }

        // e = exp(s*SCALE - MAXB)  (masked -> 0); accumulate rowsum; write P
        const bool full = (kt * 64 + 63 <= q0);
#pragma unroll
        for (int mi = 0; mi < 2; mi++)
#pragma unroll
            for (int n = 0; n < 4; n++)
#pragma unroll
                for (int e = 0; e < 4; e++) {
                    const int slot = mi * 2 + (e >> 1);
                    float p = __expf(acc[mi][n][e] * SCALE_ - MAXB_);
                    if (!full) {
                        int gi = q0 + wm + mi * 16 + (lane >> 2) + (e >> 1) * 8;
                        int gj = kt * 64 + wn + n * 8 + (lane & 3) * 2 + (e & 1);
                        if (gj > gi) p = 0.0f;
                    }
                    acc[mi][n][e] = p;
                    lsum[slot] += p;
                }
#pragma unroll
        for (int mi = 0; mi < 2; mi++) {
            int r0 = q0 + wm + mi * 16 + (lane >> 2);
#pragma unroll
            for (int n = 0; n < 4; n++) {
                int col = kt * 64 + wn + n * 8 + (lane & 3) * 2;
                *(float2*)(P + ((size_t)bh * S_ + r0) * S_ + col) =
                    make_float2(acc[mi][n][0], acc[mi][n][1]);
                *(float2*)(P + ((size_t)bh * S_ + r0 + 8) * S_ + col) =
                    make_float2(acc[mi][n][2], acc[mi][n][3]);
            }
        }

        // PV: e (A frags, bf16 hi/lo) x V^T (B frags, bf16 hi/lo), 3-term
#pragma unroll
        for (int ksl = 0; ksl < 2; ksl++) {
            uint32_t pah[2][4], pal[2][4];
#pragma unroll
            for (int mi = 0; mi < 2; mi++) {
                const int n0 = ksl * 2, n1 = ksl * 2 + 1;
                split_pack_b(acc[mi][n0][0], acc[mi][n0][1], pah[mi][0], pal[mi][0]);
                split_pack_b(acc[mi][n0][2], acc[mi][n0][3], pah[mi][1], pal[mi][1]);
                split_pack_b(acc[mi][n1][0], acc[mi][n1][1], pah[mi][2], pal[mi][2]);
                split_pack_b(acc[mi][n1][2], acc[mi][n1][3], pah[mi][3], pal[mi][3]);
            }
            const int cc = (wn >> 3) + ksl * 2;
#pragma unroll
            for (int dg = 0; dg < 8; dg++) {
                uint32_t t[4], bh2[2][2], bl2[2][2];
                ldm4(t, bV + phys(dg * 16 + fr, cc + fc));
                bh2[0][0] = t[0]; bh2[0][1] = t[2];
                bh2[1][0] = t[1]; bh2[1][1] = t[3];
                ldm4(t, bVl + phys(dg * 16 + fr, cc + fc));
                bl2[0][0] = t[0]; bl2[0][1] = t[2];
                bl2[1][0] = t[1]; bl2[1][1] = t[3];
#pragma unroll
                for (int mi = 0; mi < 2; mi++)
#pragma unroll
                    for (int sub = 0; sub < 2; sub++) {
                        const int nf = dg * 2 + sub;
                        mma_bf16(pv[mi][nf], pah[mi], bh2[sub]);
                        mma_bf16(pv[mi][nf], pah[mi], bl2[sub]);
                        mma_bf16(pv[mi][nf], pal[mi], bh2[sub]);
                    }
            }
        }
        __syncthreads();
        if (kt + 2 < nk) {
            load_stage(kt & 1, kt + 2);
            asm volatile("cp.async.commit_group;" ::: "memory");
        }
    }

    // reduce lsum across the 4 lanes of each quad
#pragma unroll
    for (int o = 1; o < 4; o <<= 1)
#pragma unroll
        for (int slot = 0; slot < 4; slot++)
            lsum[slot] += __shfl_xor_sync(0xffffffffu, lsum[slot], o);

    // combine the two col-warp groups; normalize; store octx + rowsum
    __syncthreads();
    float* ob = (float*)smem;          // 128 rows x pitch 136 floats
    float* lrow = ob + 128 * 136;
    if (wn == 32) {
#pragma unroll
        for (int mi = 0; mi < 2; mi++) {
            int r0 = wm + mi * 16 + (lane >> 2);
#pragma unroll
            for (int nf = 0; nf < 16; nf++) {
                int d = nf * 8 + (lane & 3) * 2;
                *(float2*)&ob[(size_t)r0 * 136 + d]       = make_float2(pv[mi][nf][0], pv[mi][nf][1]);
                *(float2*)&ob[(size_t)(r0 + 8) * 136 + d] = make_float2(pv[mi][nf][2], pv[mi][nf][3]);
            }
            if ((lane & 3) == 0) {
                lrow[r0]     = lsum[mi * 2];
                lrow[r0 + 8] = lsum[mi * 2 + 1];
            }
        }
    }
    __syncthreads();
    if (wn == 0) {
#pragma unroll
        for (int mi = 0; mi < 2; mi++) {
            int r0 = wm + mi * 16 + (lane >> 2);
            float lt0 = lsum[mi * 2] + lrow[r0];
            float lt1 = lsum[mi * 2 + 1] + lrow[r0 + 8];
            float inv0 = 1.0f / lt0;
            float inv1 = 1.0f / lt1;
            if ((lane & 3) == 0) {
                rowsum[(size_t)bh * S_ + q0 + r0]     = lt0;
                rowsum[(size_t)bh * S_ + q0 + r0 + 8] = lt1;
            }
#pragma unroll
            for (int nf = 0; nf < 16; nf++) {
                int d = nf * 8 + (lane & 3) * 2;
                float2 a0 = *(float2*)&ob[(size_t)r0 * 136 + d];
                float2 a1 = *(float2*)&ob[(size_t)(r0 + 8) * 136 + d];
                float* o0 = octx + ((size_t)(b * S_ + q0 + r0) * NH_ + h) * D_ + d;
                float* o1 = octx + ((size_t)(b * S_ + q0 + r0 + 8) * NH_ + h) * D_ + d;
                *(float2*)o0 = make_float2((pv[mi][nf][0] + a0.x) * inv0, (pv[mi][nf][1] + a0.y) * inv0);
                *(float2*)o1 = make_float2((pv[mi][nf][2] + a1.x) * inv1, (pv[mi][nf][3] + a1.y) * inv1);
            }
        }
    }
}

// -------- fixup: normalize written P region by 1/rowsum, zero the rest --------
__global__ __launch_bounds__(128) void normalize_zero(float* __restrict__ P,
                                                      const float* __restrict__ rowsum) {
    const int row = blockIdx.x;          // bh*S + i
    const int i = row & (S_ - 1);
    const int jend = ((i >> 7) + 1) << 7;
    const float inv = 1.0f / rowsum[row];
    float* p = P + (size_t)row * S_;
    const int t4 = threadIdx.x * 4;
    for (int j = t4; j < jend; j += 512) {
        float4 v = *(float4*)(p + j);
        v.x *= inv; v.y *= inv; v.z *= inv; v.w *= inv;
        *(float4*)(p + j) = v;
    }
    const float4 z = {0, 0, 0, 0};
    for (int j = jend + t4; j < S_; j += 512)
        *(float4*)(p + j) = z;
}

// ---------------- launch (graph-capturable fork/join on a side stream) --------
extern "C" void kernel_launch(void* const* d_in, const int* in_sizes, int n_in,
                              void* d_out, int out_size) {
    const float* hidden = (const float*)d_in[0];
    const float* cosb   = (const float*)d_in[1];
    const float* sinb   = (const float*)d_in[2];
    const float* Wq     = (const float*)d_in[4];
    const float* Wk     = (const float*)d_in[5];
    const float* Wv     = (const float*)d_in[6];
    const float* Wo     = (const float*)d_in[7];
    const float* qnw    = (const float*)d_in[8];
    const float* knw    = (const float*)d_in[9];

    float* out = (float*)d_out;
    const size_t ao_elems = (size_t)MT_ * HID_;
    float* P = out + ao_elems;

    float *qkv, *octx, *rsum;
    __half *ahi, *alo, *wqh, *woh, *ohi, *olo, *qhv, *qlv, *khv;
    __nv_bfloat16 *vth, *vtl;
    cudaGetSymbolAddress((void**)&qkv,  g_qkv);
    cudaGetSymbolAddress((void**)&octx, g_octx);
    cudaGetSymbolAddress((void**)&rsum, g_rowsum);
    cudaGetSymbolAddress((void**)&ahi,  g_ahi);
    cudaGetSymbolAddress((void**)&alo,  g_alo);
    cudaGetSymbolAddress((void**)&wqh,  g_wqkvh);
    cudaGetSymbolAddress((void**)&woh,  g_woh);
    cudaGetSymbolAddress((void**)&ohi,  g_ohi);
    cudaGetSymbolAddress((void**)&olo,  g_olo);
    cudaGetSymbolAddress((void**)&qhv,  g_qh);
    cudaGetSymbolAddress((void**)&qlv,  g_ql);
    cudaGetSymbolAddress((void**)&khv,  g_kh);
    cudaGetSymbolAddress((void**)&vth,  g_vth);
    cudaGetSymbolAddress((void**)&vtl,  g_vtl);

    cudaFuncSetAttribute(gemm_f16x2, cudaFuncAttributeMaxDynamicSharedMemorySize, GEMM_SMEM);
    cudaFuncSetAttribute(attn_fused, cudaFuncAttributeMaxDynamicSharedMemorySize, P2_SMEM);

    cudaStream_t s2;
    cudaStreamCreate(&s2);
    cudaEvent_t e1, e2, e3, e4, e5, e6;
    cudaEventCreateWithFlags(&e1, cudaEventDisableTiming);
    cudaEventCreateWithFlags(&e2, cudaEventDisableTiming);
    cudaEventCreateWithFlags(&e3, cudaEventDisableTiming);
    cudaEventCreateWithFlags(&e4, cudaEventDisableTiming);
    cudaEventCreateWithFlags(&e5, cudaEventDisableTiming);
    cudaEventCreateWithFlags(&e6, cudaEventDisableTiming);

    // ---- fork 1: weight transposes (s2) || hidden split (default) ----
    cudaEventRecord(e1, 0);
    cudaStreamWaitEvent(s2, e1, 0);
    transpose_half<<<dim3(4096 / 32, KK_ / 32), dim3(32, 8), 0, s2>>>(Wq, wqh, 4096);
    transpose_half<<<dim3(512 / 32,  KK_ / 32), dim3(32, 8), 0, s2>>>(Wk, wqh + (size_t)4096 * KK_, 512);
    transpose_half<<<dim3(512 / 32,  KK_ / 32), dim3(32, 8), 0, s2>>>(Wv, wqh + (size_t)4608 * KK_, 512);
    transpose_half<<<dim3(2048 / 32, KK_ / 32), dim3(32, 8), 0, s2>>>(Wo, woh, 2048);
    cudaEventRecord(e2, s2);
    {
        int n4 = (int)((size_t)MT_ * KK_ / 4);
        split_fp16<<<(n4 + 255) / 256, 256>>>(hidden, ahi, alo, n4);
    }
    cudaStreamWaitEvent(0, e2, 0);

    // fused QKV projection (fp16 2-term)
    gemm_f16x2<<<dim3(NQKV_ / 128, MT_ / 128), 256, GEMM_SMEM>>>(ahi, alo, wqh, qkv, NQKV_);

    // ---- fork 2: norm_k + v_trans (s2) || norm_q (default) ----
    cudaEventRecord(e3, 0);
    cudaStreamWaitEvent(s2, e3, 0);
    norm_rope_k_h<<<B_ * S_ * NKV_, 128, 0, s2>>>(qkv, cosb, sinb, knw, khv);
    v_trans_split<<<dim3(S_ / 32, D_ / 32, B_ * NKV_), dim3(32, 8), 0, s2>>>(qkv, vth, vtl);
    cudaEventRecord(e4, s2);
    norm_rope_q_h<<<B_ * S_ * NH_, 128>>>(qkv, cosb, sinb, qnw, qhv, qlv);
    cudaStreamWaitEvent(0, e4, 0);

    // fused single-pass attention (heavy CTAs first)
    attn_fused<<<dim3(S_ / 128, B_ * NH_), 256, P2_SMEM>>>(qhv, qlv, khv, vth, vtl,
                                                           rsum, P, octx);

    // ---- fork 3: P normalize/zero (s2) || gate + Wo GEMM (default) ----
    cudaEventRecord(e5, 0);
    cudaStreamWaitEvent(s2, e5, 0);
    normalize_zero<<<B_ * NH_ * S_, 128, 0, s2>>>(P, rsum);
    cudaEventRecord(e6, s2);
    gate_split<<<(int)(((size_t)MT_ * 2048 / 4) / 256), 256>>>(qkv, octx, ohi, olo);
    gemm_f16x2<<<dim3(2048 / 128, MT_ / 128), 256, GEMM_SMEM>>>(ohi, olo, woh, out, 2048);
    cudaStreamWaitEvent(0, e6, 0);

    cudaEventDestroy(e1); cudaEventDestroy(e2); cudaEventDestroy(e3);
    cudaEventDestroy(e4); cudaEventDestroy(e5); cudaEventDestroy(e6);
    cudaStreamDestroy(s2);
}

// round 17
// speedup vs baseline: 1.0514x; 1.0220x over previous
#include <cuda_runtime.h>
#include <cuda_fp16.h>
#include <cuda_bf16.h>
#include <cstdint>

#define B_  4
#define S_  2048
#define HID_ 2048
#define NH_ 16
#define NKV_ 4
#define D_  128
#define EPS_ 1e-6f
#define SCALE_ 0.08838834764831845f   // 128^-0.5
#define MAXB_ 11.5f                   // score bound: sqrt(128)*sqrt(128)*SCALE=11.314

#define MT_  8192     // B*S rows
#define KK_  2048     // GEMM K (always HID_)
#define NQKV_ 5120    // fused projection width: 4096 (q,gate) + 512 (k) + 512 (v)

// ---------------- scratch (static __device__, allocation-free) ----------------
__device__ float g_qkv [(size_t)MT_*NQKV_];
__device__ float g_octx[(size_t)MT_*2048];
__device__ float g_rowsum[(size_t)B_*NH_*S_];
__device__ __half g_ahi[(size_t)MT_*KK_],  g_alo[(size_t)MT_*KK_];
__device__ __half g_wqkvh[(size_t)NQKV_*KK_];
__device__ __half g_woh[(size_t)2048*KK_];
__device__ __half g_ohi[(size_t)MT_*2048], g_olo[(size_t)MT_*2048];
__device__ __half g_qh[(size_t)B_*NH_*S_*D_], g_ql[(size_t)B_*NH_*S_*D_];
__device__ __half g_kh[(size_t)B_*NKV_*S_*D_];
__device__ __nv_bfloat16 g_vth[(size_t)B_*NKV_*D_*S_], g_vtl[(size_t)B_*NKV_*D_*S_];

// ================= PTX helpers (family-target-safe: sm_80+ features only) =====
__device__ __forceinline__ uint32_t smem_u32(const void* p) {
    uint32_t a;
    asm("{ .reg .u64 t; cvta.to.shared.u64 t, %1; cvt.u32.u64 %0, t; }" : "=r"(a) : "l"(p));
    return a;
}
__device__ __forceinline__ void cp16(uint32_t s, const void* g) {
    asm volatile("cp.async.cg.shared.global [%0], [%1], 16;" :: "r"(s), "l"(g));
}
__device__ __forceinline__ void ldm4(uint32_t* r, uint32_t addr) {
    asm volatile("ldmatrix.sync.aligned.m8n8.x4.shared.b16 {%0,%1,%2,%3}, [%4];"
                 : "=r"(r[0]), "=r"(r[1]), "=r"(r[2]), "=r"(r[3]) : "r"(addr));
}
__device__ __forceinline__ void mma_f16(float* c, const uint32_t* a, const uint32_t* b) {
    asm volatile("mma.sync.aligned.m16n8k16.row.col.f32.f16.f16.f32 "
                 "{%0,%1,%2,%3}, {%4,%5,%6,%7}, {%8,%9}, {%0,%1,%2,%3};"
                 : "+f"(c[0]), "+f"(c[1]), "+f"(c[2]), "+f"(c[3])
                 : "r"(a[0]), "r"(a[1]), "r"(a[2]), "r"(a[3]), "r"(b[0]), "r"(b[1]));
}
__device__ __forceinline__ void mma_bf16(float* c, const uint32_t* a, const uint32_t* b) {
    asm volatile("mma.sync.aligned.m16n8k16.row.col.f32.bf16.bf16.f32 "
                 "{%0,%1,%2,%3}, {%4,%5,%6,%7}, {%8,%9}, {%0,%1,%2,%3};"
                 : "+f"(c[0]), "+f"(c[1]), "+f"(c[2]), "+f"(c[3])
                 : "r"(a[0]), "r"(a[1]), "r"(a[2]), "r"(a[3]), "r"(b[0]), "r"(b[1]));
}
__device__ __forceinline__ uint32_t phys(int r, int c) {
    return (uint32_t)(r * 128 + ((c ^ (r & 7)) << 4));
}
__device__ __forceinline__ uint32_t phys256(int r, int c) {
    return (uint32_t)(r * 256 + (((c & 7) ^ (r & 7)) << 4) + ((c & 8) << 4));
}
__device__ __forceinline__ void split_pack_h(float a, float b, uint32_t& hi, uint32_t& lo) {
    __half ha = __float2half(a), hb = __float2half(b);
    __half la = __float2half(a - __half2float(ha));
    __half lb = __float2half(b - __half2float(hb));
    __half2 H(ha, hb), L(la, lb);
    hi = *(uint32_t*)&H;
    lo = *(uint32_t*)&L;
}
__device__ __forceinline__ void split_pack_b(float a, float b, uint32_t& hi, uint32_t& lo) {
    __nv_bfloat16 ha = __float2bfloat16(a), hb = __float2bfloat16(b);
    __nv_bfloat16 la = __float2bfloat16(a - __bfloat162float(ha));
    __nv_bfloat16 lb = __float2bfloat16(b - __bfloat162float(hb));
    __nv_bfloat162 H(ha, hb), L(la, lb);
    hi = *(uint32_t*)&H;
    lo = *(uint32_t*)&L;
}

#define STG_BYTES 49152          // per stage: Ah|Al|Bh (gemm) or Kh|Vh|Vl (attn), 16KB each
#define GEMM_SMEM (3 * STG_BYTES)

// ==== fp16 2-term GEMM: C = (Ah+Al)*Bh^T, 3-stage pipe (R10-proven) ====
__global__ __launch_bounds__(256, 1) void gemm_f16x2(
    const __half* __restrict__ Ahi, const __half* __restrict__ Alo,
    const __half* __restrict__ Bhi, float* __restrict__ C, int N) {
    extern __shared__ char smem[];
    const uint32_t sb = smem_u32(smem);
    const int tid = threadIdx.x, wid = tid >> 5, lane = tid & 31;
    const int m0 = blockIdx.y * 128, n0 = blockIdx.x * 128;
    const int NKI = KK_ / 64;    // 32 iters

    const __half* ah = Ahi + (size_t)m0 * KK_;
    const __half* al = Alo + (size_t)m0 * KK_;
    const __half* bh = Bhi + (size_t)n0 * KK_;

    auto load_stage = [&](int st, int it) {
        const uint32_t base = sb + st * STG_BYTES;
        const int k0 = it * 64;
        for (int q = tid; q < 3072; q += 256) {
            int reg = q >> 10, qq = q & 1023;
            int r = qq >> 3, c = qq & 7;
            const __half* src = (reg == 0) ? ah : (reg == 1) ? al : bh;
            cp16(base + reg * 16384 + phys(r, c), src + (size_t)r * KK_ + k0 + c * 8);
        }
        asm volatile("cp.async.commit_group;" ::: "memory");
    };

    load_stage(0, 0);
    load_stage(1, 1);
    load_stage(2, 2);

    const int wm = (wid & 3) * 32;
    const int wn = (wid >> 2) * 64;
    float acc[2][8][4];
#pragma unroll
    for (int i = 0; i < 2; i++)
#pragma unroll
        for (int j = 0; j < 8; j++)
#pragma unroll
            for (int q = 0; q < 4; q++) acc[i][j][q] = 0.0f;

    const int fr = (lane & 7) + ((lane >> 3) & 1) * 8;
    const int fc = lane >> 4;

    for (int i = 0; i < NKI; i++) {
        if (i < NKI - 2)       asm volatile("cp.async.wait_group 2;" ::: "memory");
        else if (i == NKI - 2) asm volatile("cp.async.wait_group 1;" ::: "memory");
        else                   asm volatile("cp.async.wait_group 0;" ::: "memory");
        __syncthreads();

        const int st = i % 3;
        const uint32_t bA = sb + st * STG_BYTES;
        const uint32_t bAl = bA + 16384, bB = bA + 32768;
#pragma unroll
        for (int s = 0; s < 4; s++) {
            uint32_t ahf[2][4], alf[2][4], bhf[8][2];
#pragma unroll
            for (int mi = 0; mi < 2; mi++) {
                int r = wm + mi * 16 + fr;
                uint32_t off = phys(r, s * 2 + fc);
                ldm4(ahf[mi], bA + off);
                ldm4(alf[mi], bAl + off);
            }
#pragma unroll
            for (int ng = 0; ng < 4; ng++) {
                int r = wn + ng * 16 + fr;
                uint32_t off = phys(r, s * 2 + fc);
                uint32_t t[4];
                ldm4(t, bB + off);
                bhf[ng * 2][0] = t[0]; bhf[ng * 2][1] = t[2];
                bhf[ng * 2 + 1][0] = t[1]; bhf[ng * 2 + 1][1] = t[3];
            }
#pragma unroll
            for (int mi = 0; mi < 2; mi++)
#pragma unroll
                for (int n = 0; n < 8; n++) {
                    mma_f16(acc[mi][n], ahf[mi], bhf[n]);
                    mma_f16(acc[mi][n], alf[mi], bhf[n]);
                }
        }
        __syncthreads();
        if (i + 3 < NKI) load_stage(st, i + 3);
    }

#pragma unroll
    for (int mi = 0; mi < 2; mi++) {
        int r0 = m0 + wm + mi * 16 + (lane >> 2);
#pragma unroll
        for (int n = 0; n < 8; n++) {
            int col = n0 + wn + n * 8 + (lane & 3) * 2;
            *(float2*)(C + (size_t)r0 * N + col)       = make_float2(acc[mi][n][0], acc[mi][n][1]);
            *(float2*)(C + (size_t)(r0 + 8) * N + col) = make_float2(acc[mi][n][2], acc[mi][n][3]);
        }
    }
}

// ============ fp32 -> fp16 hi/lo split ============
__global__ __launch_bounds__(256) void split_fp16(const float* __restrict__ x,
                                                  __half* __restrict__ hi,
                                                  __half* __restrict__ lo,
                                                  int n4) {
    int i = blockIdx.x * 256 + threadIdx.x;
    if (i >= n4) return;
    float4 v = ((const float4*)x)[i];
    uint32_t h01, l01, h23, l23;
    split_pack_h(v.x, v.y, h01, l01);
    split_pack_h(v.z, v.w, h23, l23);
    ((uint32_t*)hi)[2 * i]     = h01;
    ((uint32_t*)hi)[2 * i + 1] = h23;
    ((uint32_t*)lo)[2 * i]     = l01;
    ((uint32_t*)lo)[2 * i + 1] = l23;
}

// ============ gate: (octx * sigmoid(gate)) -> fp16 hi/lo ============
__global__ __launch_bounds__(256) void gate_split(const float* __restrict__ qkv,
                                                  const float* __restrict__ octx,
                                                  __half* __restrict__ hi,
                                                  __half* __restrict__ lo) {
    size_t i4 = (size_t)blockIdx.x * blockDim.x + threadIdx.x;
    size_t e = i4 * 4;
    int d = (int)(e % D_);
    int h = (int)((e / D_) % NH_);
    size_t bs = e / (D_ * NH_);
    const float4 gv = *(const float4*)(qkv + bs * NQKV_ + h * (2 * D_) + D_ + d);
    float4 ov = *(const float4*)(octx + e);
    ov.x *= 1.0f / (1.0f + __expf(-gv.x));
    ov.y *= 1.0f / (1.0f + __expf(-gv.y));
    ov.z *= 1.0f / (1.0f + __expf(-gv.z));
    ov.w *= 1.0f / (1.0f + __expf(-gv.w));
    uint32_t h01, l01, h23, l23;
    split_pack_h(ov.x, ov.y, h01, l01);
    split_pack_h(ov.z, ov.w, h23, l23);
    ((uint32_t*)hi)[2 * i4]     = h01;
    ((uint32_t*)hi)[2 * i4 + 1] = h23;
    ((uint32_t*)lo)[2 * i4]     = l01;
    ((uint32_t*)lo)[2 * i4 + 1] = l23;
}

// ============ W[K,N] fp32 -> Wt fp16 [N,K] (round only) ============
__global__ __launch_bounds__(256) void transpose_half(const float* __restrict__ W,
                                                      __half* __restrict__ thi,
                                                      int N) {
    __shared__ float t[32][33];
    const int n0 = blockIdx.x * 32, k0 = blockIdx.y * 32;
    const int tx = threadIdx.x, ty = threadIdx.y;
    for (int i = ty; i < 32; i += 8)
        t[i][tx] = W[(size_t)(k0 + i) * N + n0 + tx];
    __syncthreads();
    for (int i = ty; i < 32; i += 8)
        thi[(size_t)(n0 + i) * KK_ + k0 + tx] = __float2half(t[tx][i]);
}

// ============ V (cols [4608,5120) of qkv) -> V^T bf16 hi/lo (b,kh,d,s) ========
__global__ __launch_bounds__(256) void v_trans_split(const float* __restrict__ qkv,
                                                     __nv_bfloat16* __restrict__ vth,
                                                     __nv_bfloat16* __restrict__ vtl) {
    __shared__ float t[32][33];
    const int bk = blockIdx.z;
    const int b = bk >> 2, kv = bk & 3;
    const int s0 = blockIdx.x * 32, d0 = blockIdx.y * 32;
    const int tx = threadIdx.x, ty = threadIdx.y;
    for (int i = ty; i < 32; i += 8)
        t[i][tx] = qkv[(size_t)(b * S_ + s0 + i) * NQKV_ + 4608 + kv * D_ + d0 + tx];
    __syncthreads();
    for (int i = ty; i < 32; i += 8) {
        float val = t[tx][i];
        __nv_bfloat16 h = __float2bfloat16(val);
        __nv_bfloat16 l = __float2bfloat16(val - __bfloat162float(h));
        size_t o = ((size_t)(b * NKV_ + kv) * D_ + d0 + i) * S_ + s0 + tx;
        vth[o] = h;
        vtl[o] = l;
    }
}

// ---------- RMSNorm + RoPE, warp-per-head (shuffle-only, no smem/sync) --------
__global__ __launch_bounds__(256) void norm_rope_q_w(const float* __restrict__ qkv,
                                                     const float* __restrict__ cosb,
                                                     const float* __restrict__ sinb,
                                                     const float* __restrict__ w,
                                                     __half* __restrict__ qh,
                                                     __half* __restrict__ ql) {
    const int wi = blockIdx.x * 8 + (threadIdx.x >> 5);    // (bs,h) index
    const int lane = threadIdx.x & 31;
    const int h = wi % NH_;
    const int bs = wi / NH_;
    const float4 x = *(const float4*)(qkv + (size_t)bs * NQKV_ + h * (2 * D_) + lane * 4);
    float sq = x.x * x.x + x.y * x.y + x.z * x.z + x.w * x.w;
#pragma unroll
    for (int o = 16; o > 0; o >>= 1) sq += __shfl_xor_sync(0xffffffffu, sq, o);
    const float rms = rsqrtf(sq * (1.0f / D_) + EPS_);
    const float4 w4 = *(const float4*)(w + lane * 4);
    float xn0 = x.x * rms * (1.0f + w4.x);
    float xn1 = x.y * rms * (1.0f + w4.y);
    float xn2 = x.z * rms * (1.0f + w4.z);
    float xn3 = x.w * rms * (1.0f + w4.w);
    const float sgn = (lane < 16) ? -1.0f : 1.0f;
    float r0 = sgn * __shfl_xor_sync(0xffffffffu, xn0, 16);
    float r1 = sgn * __shfl_xor_sync(0xffffffffu, xn1, 16);
    float r2 = sgn * __shfl_xor_sync(0xffffffffu, xn2, 16);
    float r3 = sgn * __shfl_xor_sync(0xffffffffu, xn3, 16);
    const float4 c4 = *(const float4*)(cosb + (size_t)bs * D_ + lane * 4);
    const float4 s4 = *(const float4*)(sinb + (size_t)bs * D_ + lane * 4);
    float v0 = xn0 * c4.x + r0 * s4.x;
    float v1 = xn1 * c4.y + r1 * s4.y;
    float v2 = xn2 * c4.z + r2 * s4.z;
    float v3 = xn3 * c4.w + r3 * s4.w;
    const int b = bs / S_, s = bs % S_;
    size_t o = (((size_t)b * NH_ + h) * S_ + s) * D_ + lane * 4;
    uint32_t h01, l01, h23, l23;
    split_pack_h(v0, v1, h01, l01);
    split_pack_h(v2, v3, h23, l23);
    *(uint2*)(qh + o) = make_uint2(h01, h23);
    *(uint2*)(ql + o) = make_uint2(l01, l23);
}

__global__ __launch_bounds__(256) void norm_rope_k_w(const float* __restrict__ qkv,
                                                     const float* __restrict__ cosb,
                                                     const float* __restrict__ sinb,
                                                     const float* __restrict__ w,
                                                     __half* __restrict__ kh) {
    const int wi = blockIdx.x * 8 + (threadIdx.x >> 5);
    const int lane = threadIdx.x & 31;
    const int kv = wi % NKV_;
    const int bs = wi / NKV_;
    const float4 x = *(const float4*)(qkv + (size_t)bs * NQKV_ + 4096 + kv * D_ + lane * 4);
    float sq = x.x * x.x + x.y * x.y + x.z * x.z + x.w * x.w;
#pragma unroll
    for (int o = 16; o > 0; o >>= 1) sq += __shfl_xor_sync(0xffffffffu, sq, o);
    const float rms = rsqrtf(sq * (1.0f / D_) + EPS_);
    const float4 w4 = *(const float4*)(w + lane * 4);
    float xn0 = x.x * rms * (1.0f + w4.x);
    float xn1 = x.y * rms * (1.0f + w4.y);
    float xn2 = x.z * rms * (1.0f + w4.z);
    float xn3 = x.w * rms * (1.0f + w4.w);
    const float sgn = (lane < 16) ? -1.0f : 1.0f;
    float r0 = sgn * __shfl_xor_sync(0xffffffffu, xn0, 16);
    float r1 = sgn * __shfl_xor_sync(0xffffffffu, xn1, 16);
    float r2 = sgn * __shfl_xor_sync(0xffffffffu, xn2, 16);
    float r3 = sgn * __shfl_xor_sync(0xffffffffu, xn3, 16);
    const float4 c4 = *(const float4*)(cosb + (size_t)bs * D_ + lane * 4);
    const float4 s4 = *(const float4*)(sinb + (size_t)bs * D_ + lane * 4);
    __half2 a(__float2half(xn0 * c4.x + r0 * s4.x), __float2half(xn1 * c4.y + r1 * s4.y));
    __half2 b2(__float2half(xn2 * c4.z + r2 * s4.z), __float2half(xn3 * c4.w + r3 * s4.w));
    const int b = bs / S_, s = bs % S_;
    size_t o = (((size_t)b * NKV_ + kv) * S_ + s) * D_ + lane * 4;
    *(uint2*)(kh + o) = make_uint2(*(uint32_t*)&a, *(uint32_t*)&b2);
}

// ===== single-pass fused attention: QK fp16x2 (Q hi/lo, K hi), PV bf16x3 =====
// heavy CTAs (large qt) launch first: qt = gridDim.x-1-blockIdx.x
// smem: Q hi/lo 64KB + 2 stages of (Kh fp16 16KB; Vh,Vl bf16 32KB) = 160KB
#define P2_SMEM 163840
__global__ __launch_bounds__(256, 1) void attn_fused(
    const __half* __restrict__ qh, const __half* __restrict__ ql,
    const __half* __restrict__ khb,
    const __nv_bfloat16* __restrict__ vth, const __nv_bfloat16* __restrict__ vtl,
    float* __restrict__ rowsum,
    float* __restrict__ P, float* __restrict__ octx) {
    extern __shared__ char smem[];
    const uint32_t sb = smem_u32(smem);
    const int tid = threadIdx.x, wid = tid >> 5, lane = tid & 31;
    const int qt = (int)gridDim.x - 1 - (int)blockIdx.x;   // heavy CTAs first
    const int bh = blockIdx.y;
    const int b = bh >> 4, h = bh & 15, kv = h >> 2;
    const int q0 = qt * 128;
    const int nk = 2 * qt + 2;
    const __half* qhp = qh + ((size_t)(b * NH_ + h) * S_ + q0) * D_;
    const __half* qlp = ql + ((size_t)(b * NH_ + h) * S_ + q0) * D_;
    const __half* khp = khb + (size_t)(b * NKV_ + kv) * S_ * D_;
    const __nv_bfloat16* vhp = vth + (size_t)(b * NKV_ + kv) * D_ * S_;
    const __nv_bfloat16* vlp = vtl + (size_t)(b * NKV_ + kv) * D_ * S_;

    for (int q = tid; q < 2048; q += 256) {
        int r = q >> 4, c = q & 15;
        uint32_t off = phys256(r, c);
        cp16(sb + off, qhp + (size_t)r * D_ + c * 8);
        cp16(sb + 32768 + off, qlp + (size_t)r * D_ + c * 8);
    }
    auto load_stage = [&](int st, int kt) {
        uint32_t base = sb + 65536 + st * STG_BYTES;
        const __half* sh = khp + (size_t)kt * 64 * D_;
        for (int q = tid; q < 1024; q += 256) {
            int r = q >> 4, c = q & 15;
            cp16(base + phys256(r, c), sh + (size_t)r * D_ + c * 8);
        }
        for (int q = tid; q < 1024; q += 256) {
            int r = q >> 3, c = q & 7;
            uint32_t off = phys(r, c);
            cp16(base + 16384 + off, vhp + (size_t)r * S_ + kt * 64 + c * 8);
            cp16(base + 32768 + off, vlp + (size_t)r * S_ + kt * 64 + c * 8);
        }
    };
    load_stage(0, 0);
    asm volatile("cp.async.commit_group;" ::: "memory");
    load_stage(1, 1);
    asm volatile("cp.async.commit_group;" ::: "memory");

    const int wm = (wid & 3) * 32, wn = (wid >> 2) * 32;
    const int fr = (lane & 7) + ((lane >> 3) & 1) * 8;
    const int fc = lane >> 4;

    float lsum[4] = {0.0f, 0.0f, 0.0f, 0.0f};
    float pv[2][16][4];
#pragma unroll
    for (int mi = 0; mi < 2; mi++)
#pragma unroll
        for (int n = 0; n < 16; n++)
#pragma unroll
            for (int q = 0; q < 4; q++) pv[mi][n][q] = 0.0f;

    for (int kt = 0; kt < nk; kt++) {
        if (kt == nk - 1) asm volatile("cp.async.wait_group 0;" ::: "memory");
        else              asm volatile("cp.async.wait_group 1;" ::: "memory");
        __syncthreads();
        const uint32_t stg = sb + 65536 + (kt & 1) * STG_BYTES;
        const uint32_t bK = stg, bV = stg + 16384, bVl = stg + 32768;

        float acc[2][4][4];
#pragma unroll
        for (int i = 0; i < 2; i++)
#pragma unroll
            for (int j = 0; j < 4; j++)
#pragma unroll
                for (int q = 0; q < 4; q++) acc[i][j][q] = 0.0f;

#pragma unroll
        for (int ks = 0; ks < 8; ks++) {
            uint32_t ahf[2][4], alf[2][4], bhf[4][2];
#pragma unroll
            for (int mi = 0; mi < 2; mi++) {
                uint32_t off = phys256(wm + mi * 16 + fr, ks * 2 + fc);
                ldm4(ahf[mi], sb + off);
                ldm4(alf[mi], sb + 32768 + off);
            }
#pragma unroll
            for (int ng = 0; ng < 2; ng++) {
                uint32_t off = phys256(wn + ng * 16 + fr, ks * 2 + fc);
                uint32_t t[4];
                ldm4(t, bK + off);
                bhf[ng * 2][0] = t[0]; bhf[ng * 2][1] = t[2];
                bhf[ng * 2 + 1][0] = t[1]; bhf[ng * 2 + 1][1] = t[3];
            }
#pragma unroll
            for (int mi = 0; mi < 2; mi++)
#pragma unroll
                for (int n = 0; n < 4; n++) {
                    mma_f16(acc[mi][n], ahf[mi], bhf[n]);
                    mma_f16(acc[mi][n], alf[mi], bhf[n]);
                }
        }

        // e = exp(s*SCALE - MAXB)  (masked -> 0); accumulate rowsum; write P
        const bool full = (kt * 64 + 63 <= q0);
#pragma unroll
        for (int mi = 0; mi < 2; mi++)
#pragma unroll
            for (int n = 0; n < 4; n++)
#pragma unroll
                for (int e = 0; e < 4; e++) {
                    const int slot = mi * 2 + (e >> 1);
                    float p = __expf(acc[mi][n][e] * SCALE_ - MAXB_);
                    if (!full) {
                        int gi = q0 + wm + mi * 16 + (lane >> 2) + (e >> 1) * 8;
                        int gj = kt * 64 + wn + n * 8 + (lane & 3) * 2 + (e & 1);
                        if (gj > gi) p = 0.0f;
                    }
                    acc[mi][n][e] = p;
                    lsum[slot] += p;
                }
#pragma unroll
        for (int mi = 0; mi < 2; mi++) {
            int r0 = q0 + wm + mi * 16 + (lane >> 2);
#pragma unroll
            for (int n = 0; n < 4; n++) {
                int col = kt * 64 + wn + n * 8 + (lane & 3) * 2;
                *(float2*)(P + ((size_t)bh * S_ + r0) * S_ + col) =
                    make_float2(acc[mi][n][0], acc[mi][n][1]);
                *(float2*)(P + ((size_t)bh * S_ + r0 + 8) * S_ + col) =
                    make_float2(acc[mi][n][2], acc[mi][n][3]);
            }
        }

        // PV: e (A frags, bf16 hi/lo) x V^T (B frags, bf16 hi/lo), 3-term
#pragma unroll
        for (int ksl = 0; ksl < 2; ksl++) {
            uint32_t pah[2][4], pal[2][4];
#pragma unroll
            for (int mi = 0; mi < 2; mi++) {
                const int n0 = ksl * 2, n1 = ksl * 2 + 1;
                split_pack_b(acc[mi][n0][0], acc[mi][n0][1], pah[mi][0], pal[mi][0]);
                split_pack_b(acc[mi][n0][2], acc[mi][n0][3], pah[mi][1], pal[mi][1]);
                split_pack_b(acc[mi][n1][0], acc[mi][n1][1], pah[mi][2], pal[mi][2]);
                split_pack_b(acc[mi][n1][2], acc[mi][n1][3], pah[mi][3], pal[mi][3]);
            }
            const int cc = (wn >> 3) + ksl * 2;
#pragma unroll
            for (int dg = 0; dg < 8; dg++) {
                uint32_t t[4], bh2[2][2], bl2[2][2];
                ldm4(t, bV + phys(dg * 16 + fr, cc + fc));
                bh2[0][0] = t[0]; bh2[0][1] = t[2];
                bh2[1][0] = t[1]; bh2[1][1] = t[3];
                ldm4(t, bVl + phys(dg * 16 + fr, cc + fc));
                bl2[0][0] = t[0]; bl2[0][1] = t[2];
                bl2[1][0] = t[1]; bl2[1][1] = t[3];
#pragma unroll
                for (int mi = 0; mi < 2; mi++)
#pragma unroll
                    for (int sub = 0; sub < 2; sub++) {
                        const int nf = dg * 2 + sub;
                        mma_bf16(pv[mi][nf], pah[mi], bh2[sub]);
                        mma_bf16(pv[mi][nf], pah[mi], bl2[sub]);
                        mma_bf16(pv[mi][nf], pal[mi], bh2[sub]);
                    }
            }
        }
        __syncthreads();
        if (kt + 2 < nk) {
            load_stage(kt & 1, kt + 2);
            asm volatile("cp.async.commit_group;" ::: "memory");
        }
    }

    // reduce lsum across the 4 lanes of each quad
#pragma unroll
    for (int o = 1; o < 4; o <<= 1)
#pragma unroll
        for (int slot = 0; slot < 4; slot++)
            lsum[slot] += __shfl_xor_sync(0xffffffffu, lsum[slot], o);

    // combine the two col-warp groups; normalize; store octx + rowsum
    __syncthreads();
    float* ob = (float*)smem;          // 128 rows x pitch 136 floats
    float* lrow = ob + 128 * 136;
    if (wn == 32) {
#pragma unroll
        for (int mi = 0; mi < 2; mi++) {
            int r0 = wm + mi * 16 + (lane >> 2);
#pragma unroll
            for (int nf = 0; nf < 16; nf++) {
                int d = nf * 8 + (lane & 3) * 2;
                *(float2*)&ob[(size_t)r0 * 136 + d]       = make_float2(pv[mi][nf][0], pv[mi][nf][1]);
                *(float2*)&ob[(size_t)(r0 + 8) * 136 + d] = make_float2(pv[mi][nf][2], pv[mi][nf][3]);
            }
            if ((lane & 3) == 0) {
                lrow[r0]     = lsum[mi * 2];
                lrow[r0 + 8] = lsum[mi * 2 + 1];
            }
        }
    }
    __syncthreads();
    if (wn == 0) {
#pragma unroll
        for (int mi = 0; mi < 2; mi++) {
            int r0 = wm + mi * 16 + (lane >> 2);
            float lt0 = lsum[mi * 2] + lrow[r0];
            float lt1 = lsum[mi * 2 + 1] + lrow[r0 + 8];
            float inv0 = 1.0f / lt0;
            float inv1 = 1.0f / lt1;
            if ((lane & 3) == 0) {
                rowsum[(size_t)bh * S_ + q0 + r0]     = lt0;
                rowsum[(size_t)bh * S_ + q0 + r0 + 8] = lt1;
            }
#pragma unroll
            for (int nf = 0; nf < 16; nf++) {
                int d = nf * 8 + (lane & 3) * 2;
                float2 a0 = *(float2*)&ob[(size_t)r0 * 136 + d];
                float2 a1 = *(float2*)&ob[(size_t)(r0 + 8) * 136 + d];
                float* o0 = octx + ((size_t)(b * S_ + q0 + r0) * NH_ + h) * D_ + d;
                float* o1 = octx + ((size_t)(b * S_ + q0 + r0 + 8) * NH_ + h) * D_ + d;
                *(float2*)o0 = make_float2((pv[mi][nf][0] + a0.x) * inv0, (pv[mi][nf][1] + a0.y) * inv0);
                *(float2*)o1 = make_float2((pv[mi][nf][2] + a1.x) * inv1, (pv[mi][nf][3] + a1.y) * inv1);
            }
        }
    }
}

// -------- fixup: normalize written P region by 1/rowsum, zero the rest --------
__global__ __launch_bounds__(128) void normalize_zero(float* __restrict__ P,
                                                      const float* __restrict__ rowsum) {
    const int row = blockIdx.x;          // bh*S + i
    const int i = row & (S_ - 1);
    const int jend = ((i >> 7) + 1) << 7;
    const float inv = 1.0f / rowsum[row];
    float* p = P + (size_t)row * S_;
    const int t4 = threadIdx.x * 4;
    for (int j = t4; j < jend; j += 512) {
        float4 v = *(float4*)(p + j);
        v.x *= inv; v.y *= inv; v.z *= inv; v.w *= inv;
        *(float4*)(p + j) = v;
    }
    const float4 z = {0, 0, 0, 0};
    for (int j = jend + t4; j < S_; j += 512)
        *(float4*)(p + j) = z;
}

// ---------------- launch (graph-capturable fork/join on a side stream) --------
extern "C" void kernel_launch(void* const* d_in, const int* in_sizes, int n_in,
                              void* d_out, int out_size) {
    const float* hidden = (const float*)d_in[0];
    const float* cosb   = (const float*)d_in[1];
    const float* sinb   = (const float*)d_in[2];
    const float* Wq     = (const float*)d_in[4];
    const float* Wk     = (const float*)d_in[5];
    const float* Wv     = (const float*)d_in[6];
    const float* Wo     = (const float*)d_in[7];
    const float* qnw    = (const float*)d_in[8];
    const float* knw    = (const float*)d_in[9];

    float* out = (float*)d_out;
    const size_t ao_elems = (size_t)MT_ * HID_;
    float* P = out + ao_elems;

    float *qkv, *octx, *rsum;
    __half *ahi, *alo, *wqh, *woh, *ohi, *olo, *qhv, *qlv, *khv;
    __nv_bfloat16 *vth, *vtl;
    cudaGetSymbolAddress((void**)&qkv,  g_qkv);
    cudaGetSymbolAddress((void**)&octx, g_octx);
    cudaGetSymbolAddress((void**)&rsum, g_rowsum);
    cudaGetSymbolAddress((void**)&ahi,  g_ahi);
    cudaGetSymbolAddress((void**)&alo,  g_alo);
    cudaGetSymbolAddress((void**)&wqh,  g_wqkvh);
    cudaGetSymbolAddress((void**)&woh,  g_woh);
    cudaGetSymbolAddress((void**)&ohi,  g_ohi);
    cudaGetSymbolAddress((void**)&olo,  g_olo);
    cudaGetSymbolAddress((void**)&qhv,  g_qh);
    cudaGetSymbolAddress((void**)&qlv,  g_ql);
    cudaGetSymbolAddress((void**)&khv,  g_kh);
    cudaGetSymbolAddress((void**)&vth,  g_vth);
    cudaGetSymbolAddress((void**)&vtl,  g_vtl);

    cudaFuncSetAttribute(gemm_f16x2, cudaFuncAttributeMaxDynamicSharedMemorySize, GEMM_SMEM);
    cudaFuncSetAttribute(attn_fused, cudaFuncAttributeMaxDynamicSharedMemorySize, P2_SMEM);

    cudaStream_t s2;
    cudaStreamCreate(&s2);
    cudaEvent_t e1, e2, e3, e4, e5, e6;
    cudaEventCreateWithFlags(&e1, cudaEventDisableTiming);
    cudaEventCreateWithFlags(&e2, cudaEventDisableTiming);
    cudaEventCreateWithFlags(&e3, cudaEventDisableTiming);
    cudaEventCreateWithFlags(&e4, cudaEventDisableTiming);
    cudaEventCreateWithFlags(&e5, cudaEventDisableTiming);
    cudaEventCreateWithFlags(&e6, cudaEventDisableTiming);

    // ---- fork 1: weight transposes (s2) || hidden split (default) ----
    cudaEventRecord(e1, 0);
    cudaStreamWaitEvent(s2, e1, 0);
    transpose_half<<<dim3(4096 / 32, KK_ / 32), dim3(32, 8), 0, s2>>>(Wq, wqh, 4096);
    transpose_half<<<dim3(512 / 32,  KK_ / 32), dim3(32, 8), 0, s2>>>(Wk, wqh + (size_t)4096 * KK_, 512);
    transpose_half<<<dim3(512 / 32,  KK_ / 32), dim3(32, 8), 0, s2>>>(Wv, wqh + (size_t)4608 * KK_, 512);
    transpose_half<<<dim3(2048 / 32, KK_ / 32), dim3(32, 8), 0, s2>>>(Wo, woh, 2048);
    cudaEventRecord(e2, s2);
    {
        int n4 = (int)((size_t)MT_ * KK_ / 4);
        split_fp16<<<(n4 + 255) / 256, 256>>>(hidden, ahi, alo, n4);
    }
    cudaStreamWaitEvent(0, e2, 0);

    // fused QKV projection (fp16 2-term)
    gemm_f16x2<<<dim3(NQKV_ / 128, MT_ / 128), 256, GEMM_SMEM>>>(ahi, alo, wqh, qkv, NQKV_);

    // ---- fork 2: norm_k + v_trans (s2) || norm_q (default) ----
    cudaEventRecord(e3, 0);
    cudaStreamWaitEvent(s2, e3, 0);
    norm_rope_k_w<<<B_ * S_ * NKV_ / 8, 256, 0, s2>>>(qkv, cosb, sinb, knw, khv);
    v_trans_split<<<dim3(S_ / 32, D_ / 32, B_ * NKV_), dim3(32, 8), 0, s2>>>(qkv, vth, vtl);
    cudaEventRecord(e4, s2);
    norm_rope_q_w<<<B_ * S_ * NH_ / 8, 256>>>(qkv, cosb, sinb, qnw, qhv, qlv);
    cudaStreamWaitEvent(0, e4, 0);

    // fused single-pass attention (heavy CTAs first)
    attn_fused<<<dim3(S_ / 128, B_ * NH_), 256, P2_SMEM>>>(qhv, qlv, khv, vth, vtl,
                                                           rsum, P, octx);

    // ---- fork 3: P normalize/zero (s2) || gate + Wo GEMM (default) ----
    cudaEventRecord(e5, 0);
    cudaStreamWaitEvent(s2, e5, 0);
    normalize_zero<<<B_ * NH_ * S_, 128, 0, s2>>>(P, rsum);
    cudaEventRecord(e6, s2);
    gate_split<<<(int)(((size_t)MT_ * 2048 / 4) / 256), 256>>>(qkv, octx, ohi, olo);
    gemm_f16x2<<<dim3(2048 / 128, MT_ / 128), 256, GEMM_SMEM>>>(ohi, olo, woh, out, 2048);
    cudaStreamWaitEvent(0, e6, 0);

    cudaEventDestroy(e1); cudaEventDestroy(e2); cudaEventDestroy(e3);
    cudaEventDestroy(e4); cudaEventDestroy(e5); cudaEventDestroy(e6);
    cudaStreamDestroy(s2);
}